// round 1
// baseline (speedup 1.0000x reference)
#include <cuda_runtime.h>
#include <math.h>

#define D_MODEL 1024
#define NH      16
#define DK      64
#define BB      2
#define SS      2048

// Scratch (allocation-free rule: __device__ globals)
__device__ float g_q[BB * SS * D_MODEL];
__device__ float g_k[BB * SS * D_MODEL];
__device__ float g_v[BB * SS * D_MODEL];
__device__ float g_ctx[BB * SS * D_MODEL];

// ---------------------------------------------------------------------------
// GEMM: C[M,1024] = A[M,1024] @ W[1024,1024]^T   (nn.Linear semantics)
// 64x64 C tile per 256-thread block, 16-wide K steps, 4x4 per thread.
// ---------------------------------------------------------------------------
__global__ void gemm_xwt(const float* __restrict__ A,
                         const float* __restrict__ W,
                         float* __restrict__ C) {
    const int K = 1024;
    __shared__ float As[16][65];  // [k][m], padded
    __shared__ float Bs[16][65];  // [k][n], padded

    int t = threadIdx.x;                 // 0..255
    int bm = blockIdx.y * 64;
    int bn = blockIdx.x * 64;
    int ty = t >> 4, tx = t & 15;        // 16x16 thread grid
    int lrow = t >> 2;                   // 0..63
    int lk4  = (t & 3) * 4;              // 0,4,8,12

    float acc[4][4];
#pragma unroll
    for (int i = 0; i < 4; i++)
#pragma unroll
        for (int j = 0; j < 4; j++) acc[i][j] = 0.0f;

    const float* Arow = A + (size_t)(bm + lrow) * K;
    const float* Wrow = W + (size_t)(bn + lrow) * K;

    for (int k0 = 0; k0 < K; k0 += 16) {
        float4 av = *(const float4*)(Arow + k0 + lk4);
        float4 bv = *(const float4*)(Wrow + k0 + lk4);
        As[lk4 + 0][lrow] = av.x; As[lk4 + 1][lrow] = av.y;
        As[lk4 + 2][lrow] = av.z; As[lk4 + 3][lrow] = av.w;
        Bs[lk4 + 0][lrow] = bv.x; Bs[lk4 + 1][lrow] = bv.y;
        Bs[lk4 + 2][lrow] = bv.z; Bs[lk4 + 3][lrow] = bv.w;
        __syncthreads();
#pragma unroll
        for (int k = 0; k < 16; k++) {
            float a[4], b[4];
#pragma unroll
            for (int i = 0; i < 4; i++) a[i] = As[k][ty * 4 + i];
#pragma unroll
            for (int j = 0; j < 4; j++) b[j] = Bs[k][tx * 4 + j];
#pragma unroll
            for (int i = 0; i < 4; i++)
#pragma unroll
                for (int j = 0; j < 4; j++) acc[i][j] += a[i] * b[j];
        }
        __syncthreads();
    }

#pragma unroll
    for (int i = 0; i < 4; i++) {
        float* Crow = C + (size_t)(bm + ty * 4 + i) * 1024 + bn + tx * 4;
#pragma unroll
        for (int j = 0; j < 4; j++) Crow[j] = acc[i][j];
    }
}

// ---------------------------------------------------------------------------
// RoPE in-place on (B,S,D) tensor. Thread handles the (i, i+32) pair of one
// head-slice. emb[s,i] = emb[s,i+32] = s * 10000^{-i/32}.
// rotate_half: out[i] = x[i]*c - x[i+32]*s ; out[i+32] = x[i+32]*c + x[i]*s
// ---------------------------------------------------------------------------
__global__ void rope_kernel(float* __restrict__ X) {
    int idx = blockIdx.x * blockDim.x + threadIdx.x;
    if (idx >= BB * SS * NH * 32) return;
    int i = idx & 31;
    int h = (idx >> 5) & 15;
    int s = (idx >> 9) & (SS - 1);
    int b = idx >> 20;

    double f = exp(-(double)i / 32.0 * log(10000.0));
    float ang = (float)((double)s * f);
    float sn, c;
    sincosf(ang, &sn, &c);

    size_t base = ((size_t)(b * SS + s)) * D_MODEL + h * DK + i;
    float x1 = X[base];
    float x2 = X[base + 32];
    X[base]      = x1 * c - x2 * sn;
    X[base + 32] = x2 * c + x1 * sn;
}

// ---------------------------------------------------------------------------
// Causal flash attention, fp32. Block = 64 query rows of one (b,h); 8 warps,
// each warp owns 8 rows. K/V/Q/P tiles in dynamic shared memory.
// Lane owns output dims d = 2*lane, 2*lane+1 and keys k = lane, lane+32.
// ---------------------------------------------------------------------------
#define ATTN_SMEM_FLOATS (64 * 64 + 64 * 68 + 64 * 64 + 64 * 64)
#define ATTN_SMEM_BYTES  (ATTN_SMEM_FLOATS * 4)

__global__ void attn_kernel(const float* __restrict__ Q,
                            const float* __restrict__ K,
                            const float* __restrict__ V,
                            float* __restrict__ Ctx) {
    extern __shared__ float sm[];
    float (*Qs)[64] = (float(*)[64])(sm);
    float (*Ks)[68] = (float(*)[68])(sm + 64 * 64);
    float (*Vs)[64] = (float(*)[64])(sm + 64 * 64 + 64 * 68);
    float (*Ps)[64] = (float(*)[64])(sm + 64 * 64 + 64 * 68 + 64 * 64);

    const int t = threadIdx.x;
    const int lane = t & 31;
    const int w = t >> 5;
    const int bh = blockIdx.y;
    const int b = bh >> 4, h = bh & 15;
    const int q0 = blockIdx.x * 64;
    const size_t D = D_MODEL;

    const float* Qb = Q + ((size_t)b * SS) * D + h * DK;
    const float* Kb = K + ((size_t)b * SS) * D + h * DK;
    const float* Vb = V + ((size_t)b * SS) * D + h * DK;

    // Load Q tile (64 rows x 64 dims)
#pragma unroll
    for (int j = 0; j < 4; j++) {
        int idx = t + j * 256;          // float4 slot 0..1023
        int row = idx >> 4, c4 = (idx & 15) * 4;
        *(float4*)&Qs[row][c4] = *(const float4*)&Qb[(size_t)(q0 + row) * D + c4];
    }

    float m[8], l[8], a0[8], a1[8];
#pragma unroll
    for (int r = 0; r < 8; r++) { m[r] = -INFINITY; l[r] = 0.0f; a0[r] = 0.0f; a1[r] = 0.0f; }

    const int ntiles = blockIdx.x + 1;  // causal: keys 0 .. q0+63
    const int d0 = 2 * lane;

    for (int kt = 0; kt < ntiles; kt++) {
        __syncthreads();
        const int k0g = kt * 64;
#pragma unroll
        for (int j = 0; j < 4; j++) {
            int idx = t + j * 256;
            int row = idx >> 4, c4 = (idx & 15) * 4;
            *(float4*)&Ks[row][c4] = *(const float4*)&Kb[(size_t)(k0g + row) * D + c4];
            *(float4*)&Vs[row][c4] = *(const float4*)&Vb[(size_t)(k0g + row) * D + c4];
        }
        __syncthreads();

#pragma unroll 2
        for (int r = 0; r < 8; r++) {
            const int row = w * 8 + r;
            const int q = q0 + row;
            const int kA = k0g + lane;
            const int kB = kA + 32;

            float dA = 0.0f, dB = 0.0f;
#pragma unroll
            for (int d4 = 0; d4 < 64; d4 += 4) {
                float4 qv = *(float4*)&Qs[row][d4];
                float4 ka = *(float4*)&Ks[lane][d4];
                float4 kb = *(float4*)&Ks[lane + 32][d4];
                dA += qv.x * ka.x + qv.y * ka.y + qv.z * ka.z + qv.w * ka.w;
                dB += qv.x * kb.x + qv.y * kb.y + qv.z * kb.z + qv.w * kb.w;
            }
            float s0 = (kA <= q) ? dA * 0.125f : -INFINITY;
            float s1 = (kB <= q) ? dB * 0.125f : -INFINITY;

            float mt = fmaxf(s0, s1);
#pragma unroll
            for (int o = 16; o; o >>= 1)
                mt = fmaxf(mt, __shfl_xor_sync(0xffffffffu, mt, o));
            float mn = fmaxf(m[r], mt);
            float p0 = __expf(s0 - mn);
            float p1 = __expf(s1 - mn);
            float alpha = __expf(m[r] - mn);
            m[r] = mn;
            float ps = p0 + p1;
#pragma unroll
            for (int o = 16; o; o >>= 1)
                ps += __shfl_xor_sync(0xffffffffu, ps, o);
            l[r] = l[r] * alpha + ps;

            Ps[row][lane] = p0;
            Ps[row][lane + 32] = p1;
            __syncwarp();

            float x0 = a0[r] * alpha, x1 = a1[r] * alpha;
#pragma unroll 8
            for (int k = 0; k < 64; k++) {
                float p = Ps[row][k];
                float2 vv = *(float2*)&Vs[k][d0];
                x0 += p * vv.x;
                x1 += p * vv.y;
            }
            a0[r] = x0; a1[r] = x1;
            __syncwarp();
        }
    }

#pragma unroll
    for (int r = 0; r < 8; r++) {
        int row = w * 8 + r;
        int q = q0 + row;
        float inv = 1.0f / l[r];
        float2 o;
        o.x = a0[r] * inv;
        o.y = a1[r] * inv;
        *(float2*)&Ctx[((size_t)(b * SS + q)) * D + h * DK + d0] = o;
    }
}

// ---------------------------------------------------------------------------
// Launch
// inputs: query, key, value, mask(int32, ignored: deterministically causal),
//         W_q, W_k, W_v, W_o ; output: (B,S,D) float
// ---------------------------------------------------------------------------
extern "C" void kernel_launch(void* const* d_in, const int* in_sizes, int n_in,
                              void* d_out, int out_size) {
    const float* q  = (const float*)d_in[0];
    const float* k  = (const float*)d_in[1];
    const float* v  = (const float*)d_in[2];
    const float* Wq = (const float*)d_in[4];
    const float* Wk = (const float*)d_in[5];
    const float* Wv = (const float*)d_in[6];
    const float* Wo = (const float*)d_in[7];
    float* out = (float*)d_out;

    float *gq, *gk, *gv, *gctx;
    cudaGetSymbolAddress((void**)&gq,   g_q);
    cudaGetSymbolAddress((void**)&gk,   g_k);
    cudaGetSymbolAddress((void**)&gv,   g_v);
    cudaGetSymbolAddress((void**)&gctx, g_ctx);

    dim3 ggrid(16, 64);  // (N/64, M/64) with M = B*S = 4096
    gemm_xwt<<<ggrid, 256>>>(q, Wq, gq);
    gemm_xwt<<<ggrid, 256>>>(k, Wk, gk);
    gemm_xwt<<<ggrid, 256>>>(v, Wv, gv);

    int nrope = BB * SS * NH * 32;
    rope_kernel<<<nrope / 256, 256>>>(gq);
    rope_kernel<<<nrope / 256, 256>>>(gk);

    cudaFuncSetAttribute(attn_kernel, cudaFuncAttributeMaxDynamicSharedMemorySize,
                         ATTN_SMEM_BYTES);
    attn_kernel<<<dim3(SS / 64, BB * NH), 256, ATTN_SMEM_BYTES>>>(gq, gk, gv, gctx);

    gemm_xwt<<<ggrid, 256>>>(gctx, Wo, out);
}

// round 3
// speedup vs baseline: 1.6883x; 1.6883x over previous
#include <cuda_runtime.h>
#include <cuda_bf16.h>
#include <cstdint>
#include <math.h>

#define D_MODEL 1024
#define NH      16
#define DK      64
#define BB      2
#define SS      2048
#define MTOT    (BB * SS)

// ---------------------------------------------------------------------------
// Scratch (allocation-free rule: __device__ globals)
// ---------------------------------------------------------------------------
__device__ float g_q[MTOT * D_MODEL];
__device__ float g_k[MTOT * D_MODEL];
__device__ float g_v[MTOT * D_MODEL];
__device__ float g_ctx[MTOT * D_MODEL];
__device__ __nv_bfloat16 g_act_hi[MTOT * D_MODEL];
__device__ __nv_bfloat16 g_act_lo[MTOT * D_MODEL];
__device__ __nv_bfloat16 g_w_hi[D_MODEL * D_MODEL];
__device__ __nv_bfloat16 g_w_lo[D_MODEL * D_MODEL];

// ---------------------------------------------------------------------------
// Portable PTX helpers (no 'a'-gated instructions)
// ---------------------------------------------------------------------------
__device__ __forceinline__ uint32_t smem_u32(const void* p) {
    uint32_t a;
    asm("{ .reg .u64 t; cvta.to.shared.u64 t, %1; cvt.u32.u64 %0, t; }" : "=r"(a) : "l"(p));
    return a;
}
#define CP_ASYNC16(dst, src) \
    asm volatile("cp.async.cg.shared.global [%0], [%1], 16;" :: "r"(dst), "l"(src))
#define CP_COMMIT() asm volatile("cp.async.commit_group;" ::: "memory")
#define CP_WAIT(n)  asm volatile("cp.async.wait_group %0;" :: "n"(n) : "memory")

__device__ __forceinline__ void ldm_x4(uint32_t* r, uint32_t addr) {
    asm volatile("ldmatrix.sync.aligned.m8n8.x4.shared.b16 {%0,%1,%2,%3}, [%4];"
                 : "=r"(r[0]), "=r"(r[1]), "=r"(r[2]), "=r"(r[3]) : "r"(addr));
}
__device__ __forceinline__ void mma16816(float* d, const uint32_t* a, const uint32_t* b) {
    asm volatile(
        "mma.sync.aligned.m16n8k16.row.col.f32.bf16.bf16.f32 "
        "{%0,%1,%2,%3}, {%4,%5,%6,%7}, {%8,%9}, {%0,%1,%2,%3};"
        : "+f"(d[0]), "+f"(d[1]), "+f"(d[2]), "+f"(d[3])
        : "r"(a[0]), "r"(a[1]), "r"(a[2]), "r"(a[3]), "r"(b[0]), "r"(b[1]));
}
// XOR swizzle for 64B rows: toggles 16B-slot bits 4-5 with row bits 1-2
__device__ __forceinline__ uint32_t sw64(uint32_t off) {
    return off ^ ((off >> 3) & 0x30);
}

// ---------------------------------------------------------------------------
// fp32 -> (bf16 hi, bf16 lo) split, vectorized x4
// ---------------------------------------------------------------------------
__global__ void split_bf16_kernel(const float4* __restrict__ X,
                                  uint2* __restrict__ hi, uint2* __restrict__ lo, int n4) {
    int i = blockIdx.x * blockDim.x + threadIdx.x;
    if (i >= n4) return;
    float4 v = X[i];
    __nv_bfloat16 h0 = __float2bfloat16(v.x), h1 = __float2bfloat16(v.y);
    __nv_bfloat16 h2 = __float2bfloat16(v.z), h3 = __float2bfloat16(v.w);
    __nv_bfloat16 l0 = __float2bfloat16(v.x - __bfloat162float(h0));
    __nv_bfloat16 l1 = __float2bfloat16(v.y - __bfloat162float(h1));
    __nv_bfloat16 l2 = __float2bfloat16(v.z - __bfloat162float(h2));
    __nv_bfloat16 l3 = __float2bfloat16(v.w - __bfloat162float(h3));
    uint2 H, L;
    H.x = (uint32_t)__bfloat16_as_ushort(h0) | ((uint32_t)__bfloat16_as_ushort(h1) << 16);
    H.y = (uint32_t)__bfloat16_as_ushort(h2) | ((uint32_t)__bfloat16_as_ushort(h3) << 16);
    L.x = (uint32_t)__bfloat16_as_ushort(l0) | ((uint32_t)__bfloat16_as_ushort(l1) << 16);
    L.y = (uint32_t)__bfloat16_as_ushort(l2) | ((uint32_t)__bfloat16_as_ushort(l3) << 16);
    hi[i] = H;
    lo[i] = L;
}

// ---------------------------------------------------------------------------
// mma.sync GEMM: C[M,1024] = A @ W^T, bf16 3-term split, fp32 accumulate.
// CTA 128x128, BK=32, 3-stage cp.async pipeline, 8 warps (4x2), 32x64/warp.
// ---------------------------------------------------------------------------
#define GK        1024
#define BKC       32
#define NCH       (GK / BKC)          // 32
#define TILE8K    8192                 // one 128x32 bf16 tile (64B rows)
#define STAGE_B   (4 * TILE8K)         // Ahi, Alo, Bhi, Blo
#define NSTG      3
#define GEMM_SMEM (NSTG * STAGE_B)     // 96 KB

__global__ void __launch_bounds__(256, 2) gemm_tc_kernel(
    const __nv_bfloat16* __restrict__ Ahi, const __nv_bfloat16* __restrict__ Alo,
    const __nv_bfloat16* __restrict__ Bhi, const __nv_bfloat16* __restrict__ Blo,
    float* __restrict__ C) {
    extern __shared__ char smc[];
    const uint32_t smb = smem_u32(smc);

    const int t = threadIdx.x;
    const int lane = t & 31, wid = t >> 5;
    const int warpM = wid >> 1, warpN = wid & 1;     // 4 x 2
    const int m0 = blockIdx.y * 128;
    const int n0 = blockIdx.x * 128;

    // ---- global load addressing (per thread): 8 x 16B per stage ----
    const int lrow = t >> 2;          // 0..63
    const int lc   = t & 3;           // 16B column
    const __nv_bfloat16* gb[4] = {Ahi + (size_t)m0 * GK, Alo + (size_t)m0 * GK,
                                  Bhi + (size_t)n0 * GK, Blo + (size_t)n0 * GK};

    // ---- ldmatrix offsets (within a stage, per thread) ----
    // A frags: [mf][ks]  row = warpM*32 + mf*16 + (lane&15), kb = ks*32 + (lane>>4)*16
    uint32_t aoff[2][2];
#pragma unroll
    for (int mf = 0; mf < 2; mf++)
#pragma unroll
        for (int ks = 0; ks < 2; ks++)
            aoff[mf][ks] = sw64((warpM * 32 + mf * 16 + (lane & 15)) * 64
                                + ks * 32 + (lane >> 4) * 16);
    // B frags: [nfb/2][ks] covering 2 n-frags each; nfb in {0,2,4,6}
    // row = warpN*64 + nfb*8 + ((lane>>4)<<3) + (lane&7), kb = ks*32 + ((lane>>3)&1)*16
    uint32_t boff[4][2];
#pragma unroll
    for (int p = 0; p < 4; p++)
#pragma unroll
        for (int ks = 0; ks < 2; ks++)
            boff[p][ks] = sw64((warpN * 64 + p * 16 + ((lane >> 4) << 3) + (lane & 7)) * 64
                               + ks * 32 + ((lane >> 3) & 1) * 16);

    float acc[2][8][4];
#pragma unroll
    for (int mf = 0; mf < 2; mf++)
#pragma unroll
        for (int nf = 0; nf < 8; nf++)
#pragma unroll
            for (int r = 0; r < 4; r++) acc[mf][nf][r] = 0.0f;

    // ---- stage loader ----
    auto load_stage = [&](int st, int ch) {
        const uint32_t sb = smb + st * STAGE_B;
#pragma unroll
        for (int j = 0; j < 8; j++) {
            const int tile = j >> 1;
            const int rh = (j & 1) * 64 + lrow;
            const __nv_bfloat16* g = gb[tile] + (size_t)rh * GK + ch * BKC + lc * 8;
            const uint32_t dst = sb + tile * TILE8K + sw64(rh * 64 + lc * 16);
            CP_ASYNC16(dst, g);
        }
        CP_COMMIT();
    };

    // prologue: chunks 0,1
    load_stage(0, 0);
    load_stage(1, 1);

    for (int ch = 0; ch < NCH; ch++) {
        if (ch < NCH - 2) { CP_WAIT(1); } else { CP_WAIT(0); }
        __syncthreads();

        // issue next chunk into the stage freed last iteration
        if (ch + 2 < NCH) load_stage((ch + 2) % NSTG, ch + 2);

        const uint32_t sb = smb + (ch % NSTG) * STAGE_B;
#pragma unroll
        for (int ks = 0; ks < 2; ks++) {
            uint32_t ah[2][4], al[2][4];
#pragma unroll
            for (int mf = 0; mf < 2; mf++) {
                ldm_x4(ah[mf], sb + aoff[mf][ks]);
                ldm_x4(al[mf], sb + TILE8K + aoff[mf][ks]);
            }
#pragma unroll
            for (int nh = 0; nh < 2; nh++) {
                uint32_t bh[2][4], bl[2][4];
#pragma unroll
                for (int p = 0; p < 2; p++) {
                    ldm_x4(bh[p], sb + 2 * TILE8K + boff[nh * 2 + p][ks]);
                    ldm_x4(bl[p], sb + 3 * TILE8K + boff[nh * 2 + p][ks]);
                }
#pragma unroll
                for (int mf = 0; mf < 2; mf++)
#pragma unroll
                    for (int p = 0; p < 2; p++)
#pragma unroll
                        for (int q = 0; q < 2; q++) {
                            const int nf = nh * 4 + p * 2 + q;
                            mma16816(acc[mf][nf], ah[mf], &bh[p][q * 2]);
                            mma16816(acc[mf][nf], al[mf], &bh[p][q * 2]);
                            mma16816(acc[mf][nf], ah[mf], &bl[p][q * 2]);
                        }
            }
        }
    }

    // ---- epilogue: fp32 accum -> C ----
    const int rbase = m0 + warpM * 32 + (lane >> 2);
    const int cbase = n0 + warpN * 64 + (lane & 3) * 2;
#pragma unroll
    for (int mf = 0; mf < 2; mf++)
#pragma unroll
        for (int nf = 0; nf < 8; nf++) {
            const int row = rbase + mf * 16;
            const int col = cbase + nf * 8;
            float2 v0 = {acc[mf][nf][0], acc[mf][nf][1]};
            float2 v1 = {acc[mf][nf][2], acc[mf][nf][3]};
            *(float2*)(C + (size_t)row * D_MODEL + col) = v0;
            *(float2*)(C + (size_t)(row + 8) * D_MODEL + col) = v1;
        }
}

// ---------------------------------------------------------------------------
// RoPE in-place, all-fp32
// ---------------------------------------------------------------------------
__global__ void rope_kernel(float* __restrict__ X) {
    int idx = blockIdx.x * blockDim.x + threadIdx.x;
    if (idx >= BB * SS * NH * 32) return;
    int i = idx & 31;
    int h = (idx >> 5) & 15;
    int s = (idx >> 9) & (SS - 1);
    int b = idx >> 20;

    float f = exp2f(-(float)i * 0.41524101186092155f);  // log2(10000)/32
    float ang = (float)s * f;
    float sn, c;
    sincosf(ang, &sn, &c);

    size_t base = ((size_t)(b * SS + s)) * D_MODEL + h * DK + i;
    float x1 = X[base];
    float x2 = X[base + 32];
    X[base]      = x1 * c - x2 * sn;
    X[base + 32] = x2 * c + x1 * sn;
}

// ---------------------------------------------------------------------------
// Causal flash attention, fp32 (R1-proven)
// ---------------------------------------------------------------------------
#define ATTN_SMEM_FLOATS (64 * 64 + 64 * 68 + 64 * 64 + 64 * 64)
#define ATTN_SMEM_BYTES  (ATTN_SMEM_FLOATS * 4)

__global__ void attn_kernel(const float* __restrict__ Q,
                            const float* __restrict__ K,
                            const float* __restrict__ V,
                            float* __restrict__ Ctx) {
    extern __shared__ float sm[];
    float (*Qs)[64] = (float(*)[64])(sm);
    float (*Ks)[68] = (float(*)[68])(sm + 64 * 64);
    float (*Vs)[64] = (float(*)[64])(sm + 64 * 64 + 64 * 68);
    float (*Ps)[64] = (float(*)[64])(sm + 64 * 64 + 64 * 68 + 64 * 64);

    const int t = threadIdx.x;
    const int lane = t & 31;
    const int w = t >> 5;
    const int bh = blockIdx.y;
    const int b = bh >> 4, h = bh & 15;
    const int q0 = blockIdx.x * 64;
    const size_t D = D_MODEL;

    const float* Qb = Q + ((size_t)b * SS) * D + h * DK;
    const float* Kb = K + ((size_t)b * SS) * D + h * DK;
    const float* Vb = V + ((size_t)b * SS) * D + h * DK;

#pragma unroll
    for (int j = 0; j < 4; j++) {
        int idx = t + j * 256;
        int row = idx >> 4, c4 = (idx & 15) * 4;
        *(float4*)&Qs[row][c4] = *(const float4*)&Qb[(size_t)(q0 + row) * D + c4];
    }

    float m[8], l[8], a0[8], a1[8];
#pragma unroll
    for (int r = 0; r < 8; r++) { m[r] = -INFINITY; l[r] = 0.0f; a0[r] = 0.0f; a1[r] = 0.0f; }

    const int ntiles = blockIdx.x + 1;
    const int d0 = 2 * lane;

    for (int kt = 0; kt < ntiles; kt++) {
        __syncthreads();
        const int k0g = kt * 64;
#pragma unroll
        for (int j = 0; j < 4; j++) {
            int idx = t + j * 256;
            int row = idx >> 4, c4 = (idx & 15) * 4;
            *(float4*)&Ks[row][c4] = *(const float4*)&Kb[(size_t)(k0g + row) * D + c4];
            *(float4*)&Vs[row][c4] = *(const float4*)&Vb[(size_t)(k0g + row) * D + c4];
        }
        __syncthreads();

#pragma unroll 2
        for (int r = 0; r < 8; r++) {
            const int row = w * 8 + r;
            const int q = q0 + row;
            const int kA = k0g + lane;
            const int kB = kA + 32;

            float dA = 0.0f, dB = 0.0f;
#pragma unroll
            for (int d4 = 0; d4 < 64; d4 += 4) {
                float4 qv = *(float4*)&Qs[row][d4];
                float4 ka = *(float4*)&Ks[lane][d4];
                float4 kb = *(float4*)&Ks[lane + 32][d4];
                dA += qv.x * ka.x + qv.y * ka.y + qv.z * ka.z + qv.w * ka.w;
                dB += qv.x * kb.x + qv.y * kb.y + qv.z * kb.z + qv.w * kb.w;
            }
            float s0 = (kA <= q) ? dA * 0.125f : -INFINITY;
            float s1 = (kB <= q) ? dB * 0.125f : -INFINITY;

            float mt = fmaxf(s0, s1);
#pragma unroll
            for (int o = 16; o; o >>= 1)
                mt = fmaxf(mt, __shfl_xor_sync(0xffffffffu, mt, o));
            float mn = fmaxf(m[r], mt);
            float p0 = __expf(s0 - mn);
            float p1 = __expf(s1 - mn);
            float alpha = __expf(m[r] - mn);
            m[r] = mn;
            float ps = p0 + p1;
#pragma unroll
            for (int o = 16; o; o >>= 1)
                ps += __shfl_xor_sync(0xffffffffu, ps, o);
            l[r] = l[r] * alpha + ps;

            Ps[row][lane] = p0;
            Ps[row][lane + 32] = p1;
            __syncwarp();

            float x0 = a0[r] * alpha, x1 = a1[r] * alpha;
#pragma unroll 8
            for (int k = 0; k < 64; k++) {
                float p = Ps[row][k];
                float2 vv = *(float2*)&Vs[k][d0];
                x0 += p * vv.x;
                x1 += p * vv.y;
            }
            a0[r] = x0; a1[r] = x1;
            __syncwarp();
        }
    }

#pragma unroll
    for (int r = 0; r < 8; r++) {
        int row = w * 8 + r;
        int q = q0 + row;
        float inv = 1.0f / l[r];
        float2 o;
        o.x = a0[r] * inv;
        o.y = a1[r] * inv;
        *(float2*)&Ctx[((size_t)(b * SS + q)) * D + h * DK + d0] = o;
    }
}

// ---------------------------------------------------------------------------
// Launch
// ---------------------------------------------------------------------------
extern "C" void kernel_launch(void* const* d_in, const int* in_sizes, int n_in,
                              void* d_out, int out_size) {
    const float* q  = (const float*)d_in[0];
    const float* k  = (const float*)d_in[1];
    const float* v  = (const float*)d_in[2];
    const float* Wq = (const float*)d_in[4];
    const float* Wk = (const float*)d_in[5];
    const float* Wv = (const float*)d_in[6];
    const float* Wo = (const float*)d_in[7];
    float* out = (float*)d_out;

    float *gq, *gk, *gv, *gctx;
    __nv_bfloat16 *ahi, *alo, *whi, *wlo;
    cudaGetSymbolAddress((void**)&gq,   g_q);
    cudaGetSymbolAddress((void**)&gk,   g_k);
    cudaGetSymbolAddress((void**)&gv,   g_v);
    cudaGetSymbolAddress((void**)&gctx, g_ctx);
    cudaGetSymbolAddress((void**)&ahi,  g_act_hi);
    cudaGetSymbolAddress((void**)&alo,  g_act_lo);
    cudaGetSymbolAddress((void**)&whi,  g_w_hi);
    cudaGetSymbolAddress((void**)&wlo,  g_w_lo);

    cudaFuncSetAttribute(gemm_tc_kernel, cudaFuncAttributeMaxDynamicSharedMemorySize, GEMM_SMEM);
    cudaFuncSetAttribute(attn_kernel, cudaFuncAttributeMaxDynamicSharedMemorySize, ATTN_SMEM_BYTES);

    const int nA4 = MTOT * D_MODEL / 4;
    const int nW4 = D_MODEL * D_MODEL / 4;
    dim3 ggrid(D_MODEL / 128, MTOT / 128);    // (8, 32)

    split_bf16_kernel<<<(nA4 + 255) / 256, 256>>>((const float4*)q, (uint2*)ahi, (uint2*)alo, nA4);
    split_bf16_kernel<<<(nW4 + 255) / 256, 256>>>((const float4*)Wq, (uint2*)whi, (uint2*)wlo, nW4);
    gemm_tc_kernel<<<ggrid, 256, GEMM_SMEM>>>(ahi, alo, whi, wlo, gq);

    split_bf16_kernel<<<(nA4 + 255) / 256, 256>>>((const float4*)k, (uint2*)ahi, (uint2*)alo, nA4);
    split_bf16_kernel<<<(nW4 + 255) / 256, 256>>>((const float4*)Wk, (uint2*)whi, (uint2*)wlo, nW4);
    gemm_tc_kernel<<<ggrid, 256, GEMM_SMEM>>>(ahi, alo, whi, wlo, gk);

    split_bf16_kernel<<<(nA4 + 255) / 256, 256>>>((const float4*)v, (uint2*)ahi, (uint2*)alo, nA4);
    split_bf16_kernel<<<(nW4 + 255) / 256, 256>>>((const float4*)Wv, (uint2*)whi, (uint2*)wlo, nW4);
    gemm_tc_kernel<<<ggrid, 256, GEMM_SMEM>>>(ahi, alo, whi, wlo, gv);

    int nrope = BB * SS * NH * 32;
    rope_kernel<<<nrope / 256, 256>>>(gq);
    rope_kernel<<<nrope / 256, 256>>>(gk);

    attn_kernel<<<dim3(SS / 64, BB * NH), 256, ATTN_SMEM_BYTES>>>(gq, gk, gv, gctx);

    split_bf16_kernel<<<(nA4 + 255) / 256, 256>>>((const float4*)gctx, (uint2*)ahi, (uint2*)alo, nA4);
    split_bf16_kernel<<<(nW4 + 255) / 256, 256>>>((const float4*)Wo, (uint2*)whi, (uint2*)wlo, nW4);
    gemm_tc_kernel<<<ggrid, 256, GEMM_SMEM>>>(ahi, alo, whi, wlo, out);
}

// round 4
// speedup vs baseline: 6.0541x; 3.5860x over previous
#include <cuda_runtime.h>
#include <cuda_bf16.h>
#include <cstdint>
#include <math.h>

#define D_MODEL 1024
#define NH      16
#define DK      64
#define BB      2
#define SS      2048
#define MTOT    (BB * SS)

// ---------------------------------------------------------------------------
// Scratch (allocation-free rule: __device__ globals)
// ---------------------------------------------------------------------------
__device__ float g_q[MTOT * D_MODEL];
__device__ float g_k[MTOT * D_MODEL];
__device__ float g_v[MTOT * D_MODEL];
__device__ float g_ctx[MTOT * D_MODEL];
__device__ __nv_bfloat16 g_act_hi[MTOT * D_MODEL];
__device__ __nv_bfloat16 g_act_lo[MTOT * D_MODEL];
__device__ __nv_bfloat16 g_w_hi[D_MODEL * D_MODEL];
__device__ __nv_bfloat16 g_w_lo[D_MODEL * D_MODEL];
// per-head split operands for attention: [b*NH+h][s][64]
__device__ __nv_bfloat16 g_qh_hi[MTOT * D_MODEL];
__device__ __nv_bfloat16 g_qh_lo[MTOT * D_MODEL];
__device__ __nv_bfloat16 g_kh_hi[MTOT * D_MODEL];
__device__ __nv_bfloat16 g_kh_lo[MTOT * D_MODEL];
__device__ __nv_bfloat16 g_vh_hi[MTOT * D_MODEL];
__device__ __nv_bfloat16 g_vh_lo[MTOT * D_MODEL];

// ---------------------------------------------------------------------------
// Portable PTX helpers
// ---------------------------------------------------------------------------
__device__ __forceinline__ uint32_t smem_u32(const void* p) {
    uint32_t a;
    asm("{ .reg .u64 t; cvta.to.shared.u64 t, %1; cvt.u32.u64 %0, t; }" : "=r"(a) : "l"(p));
    return a;
}
#define CP_ASYNC16(dst, src) \
    asm volatile("cp.async.cg.shared.global [%0], [%1], 16;" :: "r"(dst), "l"(src))
#define CP_COMMIT() asm volatile("cp.async.commit_group;" ::: "memory")
#define CP_WAIT(n)  asm volatile("cp.async.wait_group %0;" :: "n"(n) : "memory")

__device__ __forceinline__ void ldm_x4(uint32_t* r, uint32_t addr) {
    asm volatile("ldmatrix.sync.aligned.m8n8.x4.shared.b16 {%0,%1,%2,%3}, [%4];"
                 : "=r"(r[0]), "=r"(r[1]), "=r"(r[2]), "=r"(r[3]) : "r"(addr));
}
__device__ __forceinline__ void ldm_x4t(uint32_t* r, uint32_t addr) {
    asm volatile("ldmatrix.sync.aligned.m8n8.x4.trans.shared.b16 {%0,%1,%2,%3}, [%4];"
                 : "=r"(r[0]), "=r"(r[1]), "=r"(r[2]), "=r"(r[3]) : "r"(addr));
}
__device__ __forceinline__ void mma16816(float* d, const uint32_t* a, const uint32_t* b) {
    asm volatile(
        "mma.sync.aligned.m16n8k16.row.col.f32.bf16.bf16.f32 "
        "{%0,%1,%2,%3}, {%4,%5,%6,%7}, {%8,%9}, {%0,%1,%2,%3};"
        : "+f"(d[0]), "+f"(d[1]), "+f"(d[2]), "+f"(d[3])
        : "r"(a[0]), "r"(a[1]), "r"(a[2]), "r"(a[3]), "r"(b[0]), "r"(b[1]));
}
__device__ __forceinline__ uint32_t sw64(uint32_t off) {   // 64B rows
    return off ^ ((off >> 3) & 0x30);
}
__device__ __forceinline__ uint32_t sw128(uint32_t off) {  // 128B rows
    return off ^ ((off >> 3) & 0x70);
}
__device__ __forceinline__ uint32_t pack_bf16(float lo, float hi) {
    uint32_t r;
    asm("cvt.rn.bf16x2.f32 %0, %1, %2;" : "=r"(r) : "f"(hi), "f"(lo));
    return r;
}
// fast e^x on the FMA pipe (x <= ~1); avoids MUFU
__device__ __forceinline__ float fexp(float x) {
    float t = fmaxf(x * 1.4426950408889634f, -120.0f);
    float y = t + 12582912.0f;
    int   i = __float_as_int(y) - 0x4B400000;
    float f = t - (y - 12582912.0f);
    float p =         1.3333558146e-3f;
    p = fmaf(p, f, 9.6181291076e-3f);
    p = fmaf(p, f, 5.5504108664e-2f);
    p = fmaf(p, f, 2.4022650696e-1f);
    p = fmaf(p, f, 6.9314718056e-1f);
    p = fmaf(p, f, 1.0f);
    return __int_as_float(__float_as_int(p) + (i << 23));
}

// ---------------------------------------------------------------------------
// fp32 -> (bf16 hi, bf16 lo) split, flat layout (GEMM operands)
// ---------------------------------------------------------------------------
__global__ void split_bf16_kernel(const float4* __restrict__ X,
                                  uint2* __restrict__ hi, uint2* __restrict__ lo, int n4) {
    int i = blockIdx.x * blockDim.x + threadIdx.x;
    if (i >= n4) return;
    float4 v = X[i];
    __nv_bfloat16 h0 = __float2bfloat16(v.x), h1 = __float2bfloat16(v.y);
    __nv_bfloat16 h2 = __float2bfloat16(v.z), h3 = __float2bfloat16(v.w);
    __nv_bfloat16 l0 = __float2bfloat16(v.x - __bfloat162float(h0));
    __nv_bfloat16 l1 = __float2bfloat16(v.y - __bfloat162float(h1));
    __nv_bfloat16 l2 = __float2bfloat16(v.z - __bfloat162float(h2));
    __nv_bfloat16 l3 = __float2bfloat16(v.w - __bfloat162float(h3));
    uint2 H, L;
    H.x = (uint32_t)__bfloat16_as_ushort(h0) | ((uint32_t)__bfloat16_as_ushort(h1) << 16);
    H.y = (uint32_t)__bfloat16_as_ushort(h2) | ((uint32_t)__bfloat16_as_ushort(h3) << 16);
    L.x = (uint32_t)__bfloat16_as_ushort(l0) | ((uint32_t)__bfloat16_as_ushort(l1) << 16);
    L.y = (uint32_t)__bfloat16_as_ushort(l2) | ((uint32_t)__bfloat16_as_ushort(l3) << 16);
    hi[i] = H;
    lo[i] = L;
}

// ---------------------------------------------------------------------------
// mma.sync GEMM: C[M,1024] = A @ W^T, bf16 3-term split (R3-proven)
// ---------------------------------------------------------------------------
#define GK        1024
#define BKC       32
#define NCH       (GK / BKC)
#define TILE8K    8192
#define STAGE_B   (4 * TILE8K)
#define NSTG      3
#define GEMM_SMEM (NSTG * STAGE_B)

__global__ void __launch_bounds__(256, 2) gemm_tc_kernel(
    const __nv_bfloat16* __restrict__ Ahi, const __nv_bfloat16* __restrict__ Alo,
    const __nv_bfloat16* __restrict__ Bhi, const __nv_bfloat16* __restrict__ Blo,
    float* __restrict__ C) {
    extern __shared__ char smc[];
    const uint32_t smb = smem_u32(smc);

    const int t = threadIdx.x;
    const int lane = t & 31, wid = t >> 5;
    const int warpM = wid >> 1, warpN = wid & 1;
    const int m0 = blockIdx.y * 128;
    const int n0 = blockIdx.x * 128;

    const int lrow = t >> 2;
    const int lc   = t & 3;
    const __nv_bfloat16* gb[4] = {Ahi + (size_t)m0 * GK, Alo + (size_t)m0 * GK,
                                  Bhi + (size_t)n0 * GK, Blo + (size_t)n0 * GK};

    uint32_t aoff[2][2];
#pragma unroll
    for (int mf = 0; mf < 2; mf++)
#pragma unroll
        for (int ks = 0; ks < 2; ks++)
            aoff[mf][ks] = sw64((warpM * 32 + mf * 16 + (lane & 15)) * 64
                                + ks * 32 + (lane >> 4) * 16);
    uint32_t boff[4][2];
#pragma unroll
    for (int p = 0; p < 4; p++)
#pragma unroll
        for (int ks = 0; ks < 2; ks++)
            boff[p][ks] = sw64((warpN * 64 + p * 16 + ((lane >> 4) << 3) + (lane & 7)) * 64
                               + ks * 32 + ((lane >> 3) & 1) * 16);

    float acc[2][8][4];
#pragma unroll
    for (int mf = 0; mf < 2; mf++)
#pragma unroll
        for (int nf = 0; nf < 8; nf++)
#pragma unroll
            for (int r = 0; r < 4; r++) acc[mf][nf][r] = 0.0f;

    auto load_stage = [&](int st, int ch) {
        const uint32_t sb = smb + st * STAGE_B;
#pragma unroll
        for (int j = 0; j < 8; j++) {
            const int tile = j >> 1;
            const int rh = (j & 1) * 64 + lrow;
            const __nv_bfloat16* g = gb[tile] + (size_t)rh * GK + ch * BKC + lc * 8;
            const uint32_t dst = sb + tile * TILE8K + sw64(rh * 64 + lc * 16);
            CP_ASYNC16(dst, g);
        }
        CP_COMMIT();
    };

    load_stage(0, 0);
    load_stage(1, 1);

    for (int ch = 0; ch < NCH; ch++) {
        if (ch < NCH - 2) { CP_WAIT(1); } else { CP_WAIT(0); }
        __syncthreads();
        if (ch + 2 < NCH) load_stage((ch + 2) % NSTG, ch + 2);

        const uint32_t sb = smb + (ch % NSTG) * STAGE_B;
#pragma unroll
        for (int ks = 0; ks < 2; ks++) {
            uint32_t ah[2][4], al[2][4];
#pragma unroll
            for (int mf = 0; mf < 2; mf++) {
                ldm_x4(ah[mf], sb + aoff[mf][ks]);
                ldm_x4(al[mf], sb + TILE8K + aoff[mf][ks]);
            }
#pragma unroll
            for (int nh = 0; nh < 2; nh++) {
                uint32_t bh[2][4], bl[2][4];
#pragma unroll
                for (int p = 0; p < 2; p++) {
                    ldm_x4(bh[p], sb + 2 * TILE8K + boff[nh * 2 + p][ks]);
                    ldm_x4(bl[p], sb + 3 * TILE8K + boff[nh * 2 + p][ks]);
                }
#pragma unroll
                for (int mf = 0; mf < 2; mf++)
#pragma unroll
                    for (int p = 0; p < 2; p++)
#pragma unroll
                        for (int q = 0; q < 2; q++) {
                            const int nf = nh * 4 + p * 2 + q;
                            mma16816(acc[mf][nf], ah[mf], &bh[p][q * 2]);
                            mma16816(acc[mf][nf], al[mf], &bh[p][q * 2]);
                            mma16816(acc[mf][nf], ah[mf], &bl[p][q * 2]);
                        }
            }
        }
    }

    const int rbase = m0 + warpM * 32 + (lane >> 2);
    const int cbase = n0 + warpN * 64 + (lane & 3) * 2;
#pragma unroll
    for (int mf = 0; mf < 2; mf++)
#pragma unroll
        for (int nf = 0; nf < 8; nf++) {
            const int row = rbase + mf * 16;
            const int col = cbase + nf * 8;
            float2 v0 = {acc[mf][nf][0], acc[mf][nf][1]};
            float2 v1 = {acc[mf][nf][2], acc[mf][nf][3]};
            *(float2*)(C + (size_t)row * D_MODEL + col) = v0;
            *(float2*)(C + (size_t)(row + 8) * D_MODEL + col) = v1;
        }
}

// ---------------------------------------------------------------------------
// RoPE + per-head bf16 split: (B,S,D) fp32 -> [b*NH+h][s][64] hi/lo
// scale folded in (Q: 1/8 exact; K: 1)
// ---------------------------------------------------------------------------
__global__ void rope_split_kernel(const float* __restrict__ X,
                                  __nv_bfloat16* __restrict__ hi,
                                  __nv_bfloat16* __restrict__ lo, float scale) {
    int idx = blockIdx.x * blockDim.x + threadIdx.x;
    if (idx >= BB * SS * NH * 32) return;
    int i = idx & 31;
    int h = (idx >> 5) & 15;
    int s = (idx >> 9) & (SS - 1);
    int b = idx >> 20;

    float f = exp2f(-(float)i * 0.41524101186092155f);
    float ang = (float)s * f;
    float sn, c;
    sincosf(ang, &sn, &c);

    size_t src = ((size_t)(b * SS + s)) * D_MODEL + h * DK + i;
    float x1 = X[src], x2 = X[src + 32];
    float y1 = (x1 * c - x2 * sn) * scale;
    float y2 = (x2 * c + x1 * sn) * scale;

    size_t dst = ((size_t)(b * NH + h) * SS + s) * DK + i;
    __nv_bfloat16 h1 = __float2bfloat16(y1), h2 = __float2bfloat16(y2);
    hi[dst] = h1;
    hi[dst + 32] = h2;
    lo[dst] = __float2bfloat16(y1 - __bfloat162float(h1));
    lo[dst + 32] = __float2bfloat16(y2 - __bfloat162float(h2));
}

// V: per-head bf16 split (no rope)
__global__ void vsplit_kernel(const float4* __restrict__ X,
                              uint2* __restrict__ hi, uint2* __restrict__ lo) {
    int idx = blockIdx.x * blockDim.x + threadIdx.x;   // over MTOT*D_MODEL/4
    if (idx >= MTOT * D_MODEL / 4) return;
    int e = idx * 4;
    int d = e & (D_MODEL - 1);
    int h = d >> 6, dd = d & 63;
    int s = (e >> 10) & (SS - 1);
    int b = e >> 21;
    float4 v = X[idx];
    __nv_bfloat16 h0 = __float2bfloat16(v.x), h1 = __float2bfloat16(v.y);
    __nv_bfloat16 h2 = __float2bfloat16(v.z), h3 = __float2bfloat16(v.w);
    __nv_bfloat16 l0 = __float2bfloat16(v.x - __bfloat162float(h0));
    __nv_bfloat16 l1 = __float2bfloat16(v.y - __bfloat162float(h1));
    __nv_bfloat16 l2 = __float2bfloat16(v.z - __bfloat162float(h2));
    __nv_bfloat16 l3 = __float2bfloat16(v.w - __bfloat162float(h3));
    uint2 H, L;
    H.x = (uint32_t)__bfloat16_as_ushort(h0) | ((uint32_t)__bfloat16_as_ushort(h1) << 16);
    H.y = (uint32_t)__bfloat16_as_ushort(h2) | ((uint32_t)__bfloat16_as_ushort(h3) << 16);
    L.x = (uint32_t)__bfloat16_as_ushort(l0) | ((uint32_t)__bfloat16_as_ushort(l1) << 16);
    L.y = (uint32_t)__bfloat16_as_ushort(l2) | ((uint32_t)__bfloat16_as_ushort(l3) << 16);
    size_t dst = (((size_t)(b * NH + h) * SS + s) * DK + dd) >> 2;
    ((uint2*)hi)[dst] = H;
    ((uint2*)lo)[dst] = L;
}

// ---------------------------------------------------------------------------
// Tensor-core causal flash attention.
// CTA: 128 q-rows of one (b,h); 8 warps x 16 rows. BN=64 keys/tile.
// K/V hi/lo double-buffered via cp.async. All smem rows 128B, sw128.
// ---------------------------------------------------------------------------
#define AT_QHI   0
#define AT_QLO   16384
#define AT_STG   32768            // + st*32768; within: Khi,Klo,Vhi,Vlo @ 8KB each
#define AT_SMEM  (32768 + 2 * 32768)   // 96KB

__global__ void __launch_bounds__(256, 1) attn_tc_kernel(
    const __nv_bfloat16* __restrict__ Qhi, const __nv_bfloat16* __restrict__ Qlo,
    const __nv_bfloat16* __restrict__ Khi, const __nv_bfloat16* __restrict__ Klo,
    const __nv_bfloat16* __restrict__ Vhi, const __nv_bfloat16* __restrict__ Vlo,
    float* __restrict__ Ctx) {
    extern __shared__ char smc[];
    const uint32_t smb = smem_u32(smc);
    const int t = threadIdx.x, lane = t & 31, w = t >> 5;
    const int bx = (int)gridDim.x - 1 - (int)blockIdx.x;   // heavy CTAs first
    const int bh = blockIdx.y;
    const int q0 = bx * 128;
    const int ntk = 2 * bx + 2;
    const size_t hoff = (size_t)bh * SS * DK;

    // ---- Q loads (8 x 16B per thread over hi+lo) ----
    {
        int row = t >> 1;
        const __nv_bfloat16* qh = Qhi + hoff + (size_t)(q0 + row) * DK;
        const __nv_bfloat16* ql = Qlo + hoff + (size_t)(q0 + row) * DK;
#pragma unroll
        for (int j = 0; j < 4; j++) {
            int slot = (t & 1) * 4 + j;
            uint32_t sw = sw128(row * 128 + slot * 16);
            CP_ASYNC16(smb + AT_QHI + sw, qh + slot * 8);
            CP_ASYNC16(smb + AT_QLO + sw, ql + slot * 8);
        }
    }
    // ---- KV stage loader ----
    const int kvrow = t >> 2;
    const int kvs0 = t & 3;
    auto load_kv = [&](int st, int kt) {
        const uint32_t sb = smb + AT_STG + st * 32768;
        const size_t g = hoff + (size_t)(kt * 64 + kvrow) * DK;
#pragma unroll
        for (int j = 0; j < 2; j++) {
            int slot = kvs0 + j * 4;
            uint32_t sw = sw128(kvrow * 128 + slot * 16);
            CP_ASYNC16(sb + 0 * 8192 + sw, Khi + g + slot * 8);
            CP_ASYNC16(sb + 1 * 8192 + sw, Klo + g + slot * 8);
            CP_ASYNC16(sb + 2 * 8192 + sw, Vhi + g + slot * 8);
            CP_ASYNC16(sb + 3 * 8192 + sw, Vlo + g + slot * 8);
        }
        CP_COMMIT();
    };

    load_kv(0, 0);      // one group: Q + KV0
    CP_WAIT(0);
    __syncthreads();

    // ---- Q fragments to registers ----
    uint32_t qh[4][4], ql[4][4];
    {
        uint32_t base = (w * 16 + (lane & 15)) * 128 + (lane >> 4) * 16;
#pragma unroll
        for (int ks = 0; ks < 4; ks++) {
            uint32_t sw = sw128(base + ks * 32);
            ldm_x4(qh[ks], smb + AT_QHI + sw);
            ldm_x4(ql[ks], smb + AT_QLO + sw);
        }
    }

    float oacc[8][4];
#pragma unroll
    for (int nf = 0; nf < 8; nf++)
#pragma unroll
        for (int r = 0; r < 4; r++) oacc[nf][r] = 0.0f;
    float m0 = -1e30f, m1 = -1e30f, l0 = 0.0f, l1 = 0.0f;

    const int qw = q0 + w * 16;

    for (int ch = 0; ch < ntk; ch++) {
        __syncthreads();                       // stage (ch+1)&1 free to overwrite
        if (ch + 1 < ntk) load_kv((ch + 1) & 1, ch + 1);
        if (ch + 1 < ntk) { CP_WAIT(1); } else { CP_WAIT(0); }
        __syncthreads();

        const int k0g = ch * 64;
        if (k0g > qw + 15) continue;           // tile fully masked for this warp

        const uint32_t stg = smb + AT_STG + (ch & 1) * 32768;

        // ---- S = (Q/8) K^T, 3-term split ----
        float sacc[8][4];
#pragma unroll
        for (int nf = 0; nf < 8; nf++)
#pragma unroll
            for (int r = 0; r < 4; r++) sacc[nf][r] = 0.0f;

        const uint32_t krow = ((lane >> 4) << 3) + (lane & 7);
        const uint32_t kcol = ((lane >> 3) & 1) * 16;
#pragma unroll
        for (int ks = 0; ks < 4; ks++) {
#pragma unroll
            for (int p = 0; p < 4; p++) {
                uint32_t koff = sw128((p * 16 + krow) * 128 + ks * 32 + kcol);
                uint32_t kh[4], kl[4];
                ldm_x4(kh, stg + 0 * 8192 + koff);
                ldm_x4(kl, stg + 1 * 8192 + koff);
                mma16816(sacc[2 * p],     qh[ks], &kh[0]);
                mma16816(sacc[2 * p],     ql[ks], &kh[0]);
                mma16816(sacc[2 * p],     qh[ks], &kl[0]);
                mma16816(sacc[2 * p + 1], qh[ks], &kh[2]);
                mma16816(sacc[2 * p + 1], ql[ks], &kh[2]);
                mma16816(sacc[2 * p + 1], qh[ks], &kl[2]);
            }
        }

        const int r0 = qw + (lane >> 2), r1 = r0 + 8;
        // ---- causal mask (diagonal tiles only) ----
        if (k0g + 63 > qw) {
#pragma unroll
            for (int nf = 0; nf < 8; nf++) {
                int key = k0g + nf * 8 + (lane & 3) * 2;
                if (key     > r0) sacc[nf][0] = -1e30f;
                if (key + 1 > r0) sacc[nf][1] = -1e30f;
                if (key     > r1) sacc[nf][2] = -1e30f;
                if (key + 1 > r1) sacc[nf][3] = -1e30f;
            }
        }

        // ---- online softmax ----
        float mx0 = -1e30f, mx1 = -1e30f;
#pragma unroll
        for (int nf = 0; nf < 8; nf++) {
            mx0 = fmaxf(mx0, fmaxf(sacc[nf][0], sacc[nf][1]));
            mx1 = fmaxf(mx1, fmaxf(sacc[nf][2], sacc[nf][3]));
        }
        mx0 = fmaxf(mx0, __shfl_xor_sync(0xffffffffu, mx0, 1));
        mx0 = fmaxf(mx0, __shfl_xor_sync(0xffffffffu, mx0, 2));
        mx1 = fmaxf(mx1, __shfl_xor_sync(0xffffffffu, mx1, 1));
        mx1 = fmaxf(mx1, __shfl_xor_sync(0xffffffffu, mx1, 2));
        float mn0 = fmaxf(m0, mx0), mn1 = fmaxf(m1, mx1);
        float al0 = fexp(m0 - mn0), al1 = fexp(m1 - mn1);
        m0 = mn0; m1 = mn1;

        float rs0 = 0.0f, rs1 = 0.0f;
#pragma unroll
        for (int nf = 0; nf < 8; nf++) {
            sacc[nf][0] = fexp(sacc[nf][0] - mn0);
            sacc[nf][1] = fexp(sacc[nf][1] - mn0);
            sacc[nf][2] = fexp(sacc[nf][2] - mn1);
            sacc[nf][3] = fexp(sacc[nf][3] - mn1);
            rs0 += sacc[nf][0] + sacc[nf][1];
            rs1 += sacc[nf][2] + sacc[nf][3];
        }
        rs0 += __shfl_xor_sync(0xffffffffu, rs0, 1);
        rs0 += __shfl_xor_sync(0xffffffffu, rs0, 2);
        rs1 += __shfl_xor_sync(0xffffffffu, rs1, 1);
        rs1 += __shfl_xor_sync(0xffffffffu, rs1, 2);
        l0 = l0 * al0 + rs0;
        l1 = l1 * al1 + rs1;

        // ---- rescale O ----
#pragma unroll
        for (int nf = 0; nf < 8; nf++) {
            oacc[nf][0] *= al0; oacc[nf][1] *= al0;
            oacc[nf][2] *= al1; oacc[nf][3] *= al1;
        }

        // ---- pack P into A-frags (hi + residual lo) ----
        uint32_t ph[4][4], pl[4][4];
#pragma unroll
        for (int kf = 0; kf < 4; kf++) {
#pragma unroll
            for (int half = 0; half < 2; half++) {
                const float* c = sacc[2 * kf + half];
                uint32_t hA = pack_bf16(c[0], c[1]);
                uint32_t hB = pack_bf16(c[2], c[3]);
                float hA0 = __int_as_float((int)(hA << 16));
                float hA1 = __int_as_float((int)(hA & 0xFFFF0000u));
                float hB0 = __int_as_float((int)(hB << 16));
                float hB1 = __int_as_float((int)(hB & 0xFFFF0000u));
                ph[kf][half * 2 + 0] = hA;          // (r, k pair)
                ph[kf][half * 2 + 1] = hB;          // (r+8, k pair)
                pl[kf][half * 2 + 0] = pack_bf16(c[0] - hA0, c[1] - hA1);
                pl[kf][half * 2 + 1] = pack_bf16(c[2] - hB0, c[3] - hB1);
            }
        }
        // ph layout fix: frag order must be {a0=(r,k01), a1=(r+8,k01), a2=(r,k89), a3=(r+8,k89)}
        // half=0 produced a0,a1 ; half=1 produced a2,a3 -- matches indices 0,1,2,3. OK.

        // ---- O += P V, 3-term split ----
        const uint32_t vrow = ((lane >> 3) & 1) * 8 + (lane & 7);
        const uint32_t vcol = (lane >> 4) * 16;
#pragma unroll
        for (int kf = 0; kf < 4; kf++) {
#pragma unroll
            for (int nb = 0; nb < 4; nb++) {
                uint32_t voff = sw128((kf * 16 + vrow) * 128 + nb * 32 + vcol);
                uint32_t vh[4], vl[4];
                ldm_x4t(vh, stg + 2 * 8192 + voff);
                ldm_x4t(vl, stg + 3 * 8192 + voff);
                mma16816(oacc[2 * nb],     ph[kf], &vh[0]);
                mma16816(oacc[2 * nb],     pl[kf], &vh[0]);
                mma16816(oacc[2 * nb],     ph[kf], &vl[0]);
                mma16816(oacc[2 * nb + 1], ph[kf], &vh[2]);
                mma16816(oacc[2 * nb + 1], pl[kf], &vh[2]);
                mma16816(oacc[2 * nb + 1], ph[kf], &vl[2]);
            }
        }
    }

    // ---- epilogue: ctx (B,S,D) fp32 ----
    const int b = bh >> 4, h = bh & 15;
    const float inv0 = 1.0f / l0, inv1 = 1.0f / l1;
    const int row0 = q0 + w * 16 + (lane >> 2);
    float* p0 = Ctx + ((size_t)(b * SS + row0)) * D_MODEL + h * DK + (lane & 3) * 2;
    float* p1 = p0 + 8 * D_MODEL;
#pragma unroll
    for (int nf = 0; nf < 8; nf++) {
        float2 v0 = {oacc[nf][0] * inv0, oacc[nf][1] * inv0};
        float2 v1 = {oacc[nf][2] * inv1, oacc[nf][3] * inv1};
        *(float2*)(p0 + nf * 8) = v0;
        *(float2*)(p1 + nf * 8) = v1;
    }
}

// ---------------------------------------------------------------------------
// Launch
// ---------------------------------------------------------------------------
extern "C" void kernel_launch(void* const* d_in, const int* in_sizes, int n_in,
                              void* d_out, int out_size) {
    const float* q  = (const float*)d_in[0];
    const float* k  = (const float*)d_in[1];
    const float* v  = (const float*)d_in[2];
    const float* Wq = (const float*)d_in[4];
    const float* Wk = (const float*)d_in[5];
    const float* Wv = (const float*)d_in[6];
    const float* Wo = (const float*)d_in[7];
    float* out = (float*)d_out;

    float *gq, *gk, *gv, *gctx;
    __nv_bfloat16 *ahi, *alo, *whi, *wlo;
    __nv_bfloat16 *qhh, *qhl, *khh, *khl, *vhh, *vhl;
    cudaGetSymbolAddress((void**)&gq,   g_q);
    cudaGetSymbolAddress((void**)&gk,   g_k);
    cudaGetSymbolAddress((void**)&gv,   g_v);
    cudaGetSymbolAddress((void**)&gctx, g_ctx);
    cudaGetSymbolAddress((void**)&ahi,  g_act_hi);
    cudaGetSymbolAddress((void**)&alo,  g_act_lo);
    cudaGetSymbolAddress((void**)&whi,  g_w_hi);
    cudaGetSymbolAddress((void**)&wlo,  g_w_lo);
    cudaGetSymbolAddress((void**)&qhh,  g_qh_hi);
    cudaGetSymbolAddress((void**)&qhl,  g_qh_lo);
    cudaGetSymbolAddress((void**)&khh,  g_kh_hi);
    cudaGetSymbolAddress((void**)&khl,  g_kh_lo);
    cudaGetSymbolAddress((void**)&vhh,  g_vh_hi);
    cudaGetSymbolAddress((void**)&vhl,  g_vh_lo);

    cudaFuncSetAttribute(gemm_tc_kernel, cudaFuncAttributeMaxDynamicSharedMemorySize, GEMM_SMEM);
    cudaFuncSetAttribute(attn_tc_kernel, cudaFuncAttributeMaxDynamicSharedMemorySize, AT_SMEM);

    const int nA4 = MTOT * D_MODEL / 4;
    const int nW4 = D_MODEL * D_MODEL / 4;
    dim3 ggrid(D_MODEL / 128, MTOT / 128);

    split_bf16_kernel<<<(nA4 + 255) / 256, 256>>>((const float4*)q, (uint2*)ahi, (uint2*)alo, nA4);
    split_bf16_kernel<<<(nW4 + 255) / 256, 256>>>((const float4*)Wq, (uint2*)whi, (uint2*)wlo, nW4);
    gemm_tc_kernel<<<ggrid, 256, GEMM_SMEM>>>(ahi, alo, whi, wlo, gq);

    split_bf16_kernel<<<(nA4 + 255) / 256, 256>>>((const float4*)k, (uint2*)ahi, (uint2*)alo, nA4);
    split_bf16_kernel<<<(nW4 + 255) / 256, 256>>>((const float4*)Wk, (uint2*)whi, (uint2*)wlo, nW4);
    gemm_tc_kernel<<<ggrid, 256, GEMM_SMEM>>>(ahi, alo, whi, wlo, gk);

    split_bf16_kernel<<<(nA4 + 255) / 256, 256>>>((const float4*)v, (uint2*)ahi, (uint2*)alo, nA4);
    split_bf16_kernel<<<(nW4 + 255) / 256, 256>>>((const float4*)Wv, (uint2*)whi, (uint2*)wlo, nW4);
    gemm_tc_kernel<<<ggrid, 256, GEMM_SMEM>>>(ahi, alo, whi, wlo, gv);

    int nrope = BB * SS * NH * 32;
    rope_split_kernel<<<nrope / 256, 256>>>(gq, qhh, qhl, 0.125f);
    rope_split_kernel<<<nrope / 256, 256>>>(gk, khh, khl, 1.0f);
    vsplit_kernel<<<(nA4 + 255) / 256, 256>>>((const float4*)gv, (uint2*)vhh, (uint2*)vhl);

    attn_tc_kernel<<<dim3(SS / 128, BB * NH), 256, AT_SMEM>>>(qhh, qhl, khh, khl, vhh, vhl, gctx);

    split_bf16_kernel<<<(nA4 + 255) / 256, 256>>>((const float4*)gctx, (uint2*)ahi, (uint2*)alo, nA4);
    split_bf16_kernel<<<(nW4 + 255) / 256, 256>>>((const float4*)Wo, (uint2*)whi, (uint2*)wlo, nW4);
    gemm_tc_kernel<<<ggrid, 256, GEMM_SMEM>>>(ahi, alo, whi, wlo, out);
}

// round 5
// speedup vs baseline: 6.1910x; 1.0226x over previous
#include <cuda_runtime.h>
#include <cuda_bf16.h>
#include <cstdint>
#include <math.h>

#define D_MODEL 1024
#define NH      16
#define DK      64
#define BB      2
#define SS      2048
#define MTOT    (BB * SS)
#define KLOG2   0.41524101186092155f   // log2(10000)/32

// ---------------------------------------------------------------------------
// Scratch (allocation-free rule: __device__ globals)
// ---------------------------------------------------------------------------
// input activation splits (flat [4096][1024])
__device__ __nv_bfloat16 g_aq_hi[MTOT * D_MODEL], g_aq_lo[MTOT * D_MODEL];
__device__ __nv_bfloat16 g_ak_hi[MTOT * D_MODEL], g_ak_lo[MTOT * D_MODEL];
__device__ __nv_bfloat16 g_av_hi[MTOT * D_MODEL], g_av_lo[MTOT * D_MODEL];
// weight splits
__device__ __nv_bfloat16 g_wq_hi[D_MODEL * D_MODEL], g_wq_lo[D_MODEL * D_MODEL];
__device__ __nv_bfloat16 g_wk_hi[D_MODEL * D_MODEL], g_wk_lo[D_MODEL * D_MODEL];
__device__ __nv_bfloat16 g_wv_hi[D_MODEL * D_MODEL], g_wv_lo[D_MODEL * D_MODEL];
__device__ __nv_bfloat16 g_wo_hi[D_MODEL * D_MODEL], g_wo_lo[D_MODEL * D_MODEL];
// per-head attention operands [b*NH+h][s][64]
__device__ __nv_bfloat16 g_qh_hi[MTOT * D_MODEL], g_qh_lo[MTOT * D_MODEL];
__device__ __nv_bfloat16 g_kh_hi[MTOT * D_MODEL], g_kh_lo[MTOT * D_MODEL];
__device__ __nv_bfloat16 g_vh_hi[MTOT * D_MODEL], g_vh_lo[MTOT * D_MODEL];
// attention output splits (flat)
__device__ __nv_bfloat16 g_cx_hi[MTOT * D_MODEL], g_cx_lo[MTOT * D_MODEL];

// ---------------------------------------------------------------------------
// Portable PTX helpers
// ---------------------------------------------------------------------------
__device__ __forceinline__ uint32_t smem_u32(const void* p) {
    uint32_t a;
    asm("{ .reg .u64 t; cvta.to.shared.u64 t, %1; cvt.u32.u64 %0, t; }" : "=r"(a) : "l"(p));
    return a;
}
#define CP_ASYNC16(dst, src) \
    asm volatile("cp.async.cg.shared.global [%0], [%1], 16;" :: "r"(dst), "l"(src))
#define CP_COMMIT() asm volatile("cp.async.commit_group;" ::: "memory")
#define CP_WAIT(n)  asm volatile("cp.async.wait_group %0;" :: "n"(n) : "memory")

__device__ __forceinline__ void ldm_x4(uint32_t* r, uint32_t addr) {
    asm volatile("ldmatrix.sync.aligned.m8n8.x4.shared.b16 {%0,%1,%2,%3}, [%4];"
                 : "=r"(r[0]), "=r"(r[1]), "=r"(r[2]), "=r"(r[3]) : "r"(addr));
}
__device__ __forceinline__ void ldm_x4t(uint32_t* r, uint32_t addr) {
    asm volatile("ldmatrix.sync.aligned.m8n8.x4.trans.shared.b16 {%0,%1,%2,%3}, [%4];"
                 : "=r"(r[0]), "=r"(r[1]), "=r"(r[2]), "=r"(r[3]) : "r"(addr));
}
__device__ __forceinline__ void mma16816(float* d, const uint32_t* a, const uint32_t* b) {
    asm volatile(
        "mma.sync.aligned.m16n8k16.row.col.f32.bf16.bf16.f32 "
        "{%0,%1,%2,%3}, {%4,%5,%6,%7}, {%8,%9}, {%0,%1,%2,%3};"
        : "+f"(d[0]), "+f"(d[1]), "+f"(d[2]), "+f"(d[3])
        : "r"(a[0]), "r"(a[1]), "r"(a[2]), "r"(a[3]), "r"(b[0]), "r"(b[1]));
}
__device__ __forceinline__ uint32_t sw64(uint32_t off)  { return off ^ ((off >> 3) & 0x30); }
__device__ __forceinline__ uint32_t sw128(uint32_t off) { return off ^ ((off >> 3) & 0x70); }

__device__ __forceinline__ uint32_t pack_bf16(float lo, float hi) {
    uint32_t r;
    asm("cvt.rn.bf16x2.f32 %0, %1, %2;" : "=r"(r) : "f"(hi), "f"(lo));
    return r;
}
// split two floats into packed bf16x2 hi word + residual lo word
__device__ __forceinline__ void split2(float a, float b, uint32_t& H, uint32_t& L) {
    uint32_t h = pack_bf16(a, b);
    float ha = __int_as_float((int)(h << 16));
    float hb = __int_as_float((int)(h & 0xFFFF0000u));
    H = h;
    L = pack_bf16(a - ha, b - hb);
}
// fast e^x on the FMA pipe
__device__ __forceinline__ float fexp(float x) {
    float t = fmaxf(x * 1.4426950408889634f, -120.0f);
    float y = t + 12582912.0f;
    int   i = __float_as_int(y) - 0x4B400000;
    float f = t - (y - 12582912.0f);
    float p =         1.3333558146e-3f;
    p = fmaf(p, f, 9.6181291076e-3f);
    p = fmaf(p, f, 5.5504108664e-2f);
    p = fmaf(p, f, 2.4022650696e-1f);
    p = fmaf(p, f, 6.9314718056e-1f);
    p = fmaf(p, f, 1.0f);
    return __int_as_float(__float_as_int(p) + (i << 23));
}

// ---------------------------------------------------------------------------
// Fused splits: blockIdx.y selects which tensor (3 acts / 4 weights)
// ---------------------------------------------------------------------------
__device__ __forceinline__ void do_split4(float4 v, uint2& H, uint2& L) {
    __nv_bfloat16 h0 = __float2bfloat16(v.x), h1 = __float2bfloat16(v.y);
    __nv_bfloat16 h2 = __float2bfloat16(v.z), h3 = __float2bfloat16(v.w);
    __nv_bfloat16 l0 = __float2bfloat16(v.x - __bfloat162float(h0));
    __nv_bfloat16 l1 = __float2bfloat16(v.y - __bfloat162float(h1));
    __nv_bfloat16 l2 = __float2bfloat16(v.z - __bfloat162float(h2));
    __nv_bfloat16 l3 = __float2bfloat16(v.w - __bfloat162float(h3));
    H.x = (uint32_t)__bfloat16_as_ushort(h0) | ((uint32_t)__bfloat16_as_ushort(h1) << 16);
    H.y = (uint32_t)__bfloat16_as_ushort(h2) | ((uint32_t)__bfloat16_as_ushort(h3) << 16);
    L.x = (uint32_t)__bfloat16_as_ushort(l0) | ((uint32_t)__bfloat16_as_ushort(l1) << 16);
    L.y = (uint32_t)__bfloat16_as_ushort(l2) | ((uint32_t)__bfloat16_as_ushort(l3) << 16);
}

__global__ void split3_kernel(const float4* __restrict__ A, const float4* __restrict__ B,
                              const float4* __restrict__ C,
                              uint2* ah, uint2* al, uint2* bh, uint2* bl,
                              uint2* ch, uint2* cl, int n4) {
    int i = blockIdx.x * blockDim.x + threadIdx.x;
    if (i >= n4) return;
    const float4* src = (blockIdx.y == 0) ? A : (blockIdx.y == 1) ? B : C;
    uint2* dh = (blockIdx.y == 0) ? ah : (blockIdx.y == 1) ? bh : ch;
    uint2* dl = (blockIdx.y == 0) ? al : (blockIdx.y == 1) ? bl : cl;
    uint2 H, L;
    do_split4(src[i], H, L);
    dh[i] = H;
    dl[i] = L;
}

__global__ void split4_kernel(const float4* __restrict__ A, const float4* __restrict__ B,
                              const float4* __restrict__ C, const float4* __restrict__ D,
                              uint2* ah, uint2* al, uint2* bh, uint2* bl,
                              uint2* ch, uint2* cl, uint2* dh, uint2* dl, int n4) {
    int i = blockIdx.x * blockDim.x + threadIdx.x;
    if (i >= n4) return;
    int s = blockIdx.y;
    const float4* src = (s == 0) ? A : (s == 1) ? B : (s == 2) ? C : D;
    uint2* oh = (s == 0) ? ah : (s == 1) ? bh : (s == 2) ? ch : dh;
    uint2* ol = (s == 0) ? al : (s == 1) ? bl : (s == 2) ? cl : dl;
    uint2 H, L;
    do_split4(src[i], H, L);
    oh[i] = H;
    ol[i] = L;
}

// ---------------------------------------------------------------------------
// mma.sync GEMM: C[M,1024] = A @ W^T, bf16 3-term split.
// MODE 0: fp32 C out (flat). MODE 1: RoPE + per-head bf16 split out (scale).
// MODE 2: per-head bf16 split out.
// ---------------------------------------------------------------------------
#define GK        1024
#define BKC       32
#define NCH       (GK / BKC)
#define TILE8K    8192
#define STAGE_B   (4 * TILE8K)
#define NSTG      3
#define GEMM_SMEM (NSTG * STAGE_B)

template <int MODE>
__global__ void __launch_bounds__(256, 2) gemm_tc_kernel(
    const __nv_bfloat16* __restrict__ Ahi, const __nv_bfloat16* __restrict__ Alo,
    const __nv_bfloat16* __restrict__ Bhi, const __nv_bfloat16* __restrict__ Blo,
    float* __restrict__ C,
    __nv_bfloat16* __restrict__ Ohi, __nv_bfloat16* __restrict__ Olo, float scale) {
    extern __shared__ char smc[];
    const uint32_t smb = smem_u32(smc);

    const int t = threadIdx.x;
    const int lane = t & 31, wid = t >> 5;
    const int warpM = wid >> 1, warpN = wid & 1;
    const int m0 = blockIdx.y * 128;
    const int n0 = blockIdx.x * 128;

    const int lrow = t >> 2;
    const int lc   = t & 3;
    const __nv_bfloat16* gb[4] = {Ahi + (size_t)m0 * GK, Alo + (size_t)m0 * GK,
                                  Bhi + (size_t)n0 * GK, Blo + (size_t)n0 * GK};

    uint32_t aoff[2][2];
#pragma unroll
    for (int mf = 0; mf < 2; mf++)
#pragma unroll
        for (int ks = 0; ks < 2; ks++)
            aoff[mf][ks] = sw64((warpM * 32 + mf * 16 + (lane & 15)) * 64
                                + ks * 32 + (lane >> 4) * 16);
    uint32_t boff[4][2];
#pragma unroll
    for (int p = 0; p < 4; p++)
#pragma unroll
        for (int ks = 0; ks < 2; ks++)
            boff[p][ks] = sw64((warpN * 64 + p * 16 + ((lane >> 4) << 3) + (lane & 7)) * 64
                               + ks * 32 + ((lane >> 3) & 1) * 16);

    float acc[2][8][4];
#pragma unroll
    for (int mf = 0; mf < 2; mf++)
#pragma unroll
        for (int nf = 0; nf < 8; nf++)
#pragma unroll
            for (int r = 0; r < 4; r++) acc[mf][nf][r] = 0.0f;

    auto load_stage = [&](int st, int ch) {
        const uint32_t sb = smb + st * STAGE_B;
#pragma unroll
        for (int j = 0; j < 8; j++) {
            const int tile = j >> 1;
            const int rh = (j & 1) * 64 + lrow;
            const __nv_bfloat16* g = gb[tile] + (size_t)rh * GK + ch * BKC + lc * 8;
            const uint32_t dst = sb + tile * TILE8K + sw64(rh * 64 + lc * 16);
            CP_ASYNC16(dst, g);
        }
        CP_COMMIT();
    };

    load_stage(0, 0);
    load_stage(1, 1);

    for (int ch = 0; ch < NCH; ch++) {
        if (ch < NCH - 2) { CP_WAIT(1); } else { CP_WAIT(0); }
        __syncthreads();
        if (ch + 2 < NCH) load_stage((ch + 2) % NSTG, ch + 2);

        const uint32_t sb = smb + (ch % NSTG) * STAGE_B;
#pragma unroll
        for (int ks = 0; ks < 2; ks++) {
            uint32_t ah[2][4], al[2][4];
#pragma unroll
            for (int mf = 0; mf < 2; mf++) {
                ldm_x4(ah[mf], sb + aoff[mf][ks]);
                ldm_x4(al[mf], sb + TILE8K + aoff[mf][ks]);
            }
#pragma unroll
            for (int nh = 0; nh < 2; nh++) {
                uint32_t bh[2][4], bl[2][4];
#pragma unroll
                for (int p = 0; p < 2; p++) {
                    ldm_x4(bh[p], sb + 2 * TILE8K + boff[nh * 2 + p][ks]);
                    ldm_x4(bl[p], sb + 3 * TILE8K + boff[nh * 2 + p][ks]);
                }
#pragma unroll
                for (int mf = 0; mf < 2; mf++)
#pragma unroll
                    for (int p = 0; p < 2; p++)
#pragma unroll
                        for (int q = 0; q < 2; q++) {
                            const int nf = nh * 4 + p * 2 + q;
                            mma16816(acc[mf][nf], ah[mf], &bh[p][q * 2]);
                            mma16816(acc[mf][nf], al[mf], &bh[p][q * 2]);
                            mma16816(acc[mf][nf], ah[mf], &bl[p][q * 2]);
                        }
            }
        }
    }

    // -------- epilogues --------
    const int rbase = m0 + warpM * 32 + (lane >> 2);
    if (MODE == 0) {
        const int cbase = n0 + warpN * 64 + (lane & 3) * 2;
#pragma unroll
        for (int mf = 0; mf < 2; mf++)
#pragma unroll
            for (int nf = 0; nf < 8; nf++) {
                const int row = rbase + mf * 16;
                const int col = cbase + nf * 8;
                float2 v0 = {acc[mf][nf][0], acc[mf][nf][1]};
                float2 v1 = {acc[mf][nf][2], acc[mf][nf][3]};
                *(float2*)(C + (size_t)row * D_MODEL + col) = v0;
                *(float2*)(C + (size_t)(row + 8) * D_MODEL + col) = v1;
            }
    } else if (MODE == 1) {
        // RoPE + per-head split. head = 64-col block; pair (d, d+32) = (nf, nf+4).
        const int h = (n0 >> 6) + warpN;
#pragma unroll
        for (int mf = 0; mf < 2; mf++)
#pragma unroll
            for (int r2 = 0; r2 < 2; r2++) {
                const int gr = rbase + mf * 16 + r2 * 8;
                const int s = gr & (SS - 1), b = gr >> 11;
                const float fs = (float)s;
                __nv_bfloat16* oh = Ohi + ((size_t)(b * NH + h) * SS + s) * DK;
                __nv_bfloat16* ol = Olo + ((size_t)(b * NH + h) * SS + s) * DK;
#pragma unroll
                for (int nf = 0; nf < 4; nf++) {
                    const int i0 = (lane & 3) * 2 + nf * 8;
                    float x1a = acc[mf][nf][2 * r2],     x1b = acc[mf][nf][2 * r2 + 1];
                    float x2a = acc[mf][nf + 4][2 * r2], x2b = acc[mf][nf + 4][2 * r2 + 1];
                    float sa, ca, sb2, cb;
                    sincosf(fs * exp2f(-(float)i0 * KLOG2), &sa, &ca);
                    sincosf(fs * exp2f(-(float)(i0 + 1) * KLOG2), &sb2, &cb);
                    float y1a = (x1a * ca - x2a * sa) * scale;
                    float y1b = (x1b * cb - x2b * sb2) * scale;
                    float y2a = (x2a * ca + x1a * sa) * scale;
                    float y2b = (x2b * cb + x1b * sb2) * scale;
                    uint32_t H, L;
                    split2(y1a, y1b, H, L);
                    *(uint32_t*)(oh + i0) = H;
                    *(uint32_t*)(ol + i0) = L;
                    split2(y2a, y2b, H, L);
                    *(uint32_t*)(oh + i0 + 32) = H;
                    *(uint32_t*)(ol + i0 + 32) = L;
                }
            }
    } else {
        // per-head split only (V)
        const int h = (n0 >> 6) + warpN;
#pragma unroll
        for (int mf = 0; mf < 2; mf++)
#pragma unroll
            for (int r2 = 0; r2 < 2; r2++) {
                const int gr = rbase + mf * 16 + r2 * 8;
                const int s = gr & (SS - 1), b = gr >> 11;
                __nv_bfloat16* oh = Ohi + ((size_t)(b * NH + h) * SS + s) * DK;
                __nv_bfloat16* ol = Olo + ((size_t)(b * NH + h) * SS + s) * DK;
#pragma unroll
                for (int nf = 0; nf < 8; nf++) {
                    const int d = (lane & 3) * 2 + nf * 8;
                    uint32_t H, L;
                    split2(acc[mf][nf][2 * r2], acc[mf][nf][2 * r2 + 1], H, L);
                    *(uint32_t*)(oh + d) = H;
                    *(uint32_t*)(ol + d) = L;
                }
            }
    }
}

// ---------------------------------------------------------------------------
// Tensor-core causal flash attention; epilogue writes flat bf16 splits.
// ---------------------------------------------------------------------------
#define AT_QHI   0
#define AT_QLO   16384
#define AT_STG   32768
#define AT_SMEM  (32768 + 2 * 32768)

__global__ void __launch_bounds__(256, 1) attn_tc_kernel(
    const __nv_bfloat16* __restrict__ Qhi, const __nv_bfloat16* __restrict__ Qlo,
    const __nv_bfloat16* __restrict__ Khi, const __nv_bfloat16* __restrict__ Klo,
    const __nv_bfloat16* __restrict__ Vhi, const __nv_bfloat16* __restrict__ Vlo,
    __nv_bfloat16* __restrict__ CxHi, __nv_bfloat16* __restrict__ CxLo) {
    extern __shared__ char smc[];
    const uint32_t smb = smem_u32(smc);
    const int t = threadIdx.x, lane = t & 31, w = t >> 5;
    const int bx = (int)gridDim.x - 1 - (int)blockIdx.x;
    const int bh = blockIdx.y;
    const int q0 = bx * 128;
    const int ntk = 2 * bx + 2;
    const size_t hoff = (size_t)bh * SS * DK;

    {
        int row = t >> 1;
        const __nv_bfloat16* qh = Qhi + hoff + (size_t)(q0 + row) * DK;
        const __nv_bfloat16* ql = Qlo + hoff + (size_t)(q0 + row) * DK;
#pragma unroll
        for (int j = 0; j < 4; j++) {
            int slot = (t & 1) * 4 + j;
            uint32_t sw = sw128(row * 128 + slot * 16);
            CP_ASYNC16(smb + AT_QHI + sw, qh + slot * 8);
            CP_ASYNC16(smb + AT_QLO + sw, ql + slot * 8);
        }
    }
    const int kvrow = t >> 2;
    const int kvs0 = t & 3;
    auto load_kv = [&](int st, int kt) {
        const uint32_t sb = smb + AT_STG + st * 32768;
        const size_t g = hoff + (size_t)(kt * 64 + kvrow) * DK;
#pragma unroll
        for (int j = 0; j < 2; j++) {
            int slot = kvs0 + j * 4;
            uint32_t sw = sw128(kvrow * 128 + slot * 16);
            CP_ASYNC16(sb + 0 * 8192 + sw, Khi + g + slot * 8);
            CP_ASYNC16(sb + 1 * 8192 + sw, Klo + g + slot * 8);
            CP_ASYNC16(sb + 2 * 8192 + sw, Vhi + g + slot * 8);
            CP_ASYNC16(sb + 3 * 8192 + sw, Vlo + g + slot * 8);
        }
        CP_COMMIT();
    };

    load_kv(0, 0);
    CP_WAIT(0);
    __syncthreads();

    uint32_t qh[4][4], ql[4][4];
    {
        uint32_t base = (w * 16 + (lane & 15)) * 128 + (lane >> 4) * 16;
#pragma unroll
        for (int ks = 0; ks < 4; ks++) {
            uint32_t sw = sw128(base + ks * 32);
            ldm_x4(qh[ks], smb + AT_QHI + sw);
            ldm_x4(ql[ks], smb + AT_QLO + sw);
        }
    }

    float oacc[8][4];
#pragma unroll
    for (int nf = 0; nf < 8; nf++)
#pragma unroll
        for (int r = 0; r < 4; r++) oacc[nf][r] = 0.0f;
    float m0 = -1e30f, m1 = -1e30f, l0 = 0.0f, l1 = 0.0f;

    const int qw = q0 + w * 16;

    for (int ch = 0; ch < ntk; ch++) {
        __syncthreads();
        if (ch + 1 < ntk) load_kv((ch + 1) & 1, ch + 1);
        if (ch + 1 < ntk) { CP_WAIT(1); } else { CP_WAIT(0); }
        __syncthreads();

        const int k0g = ch * 64;
        if (k0g > qw + 15) continue;

        const uint32_t stg = smb + AT_STG + (ch & 1) * 32768;

        float sacc[8][4];
#pragma unroll
        for (int nf = 0; nf < 8; nf++)
#pragma unroll
            for (int r = 0; r < 4; r++) sacc[nf][r] = 0.0f;

        const uint32_t krow = ((lane >> 4) << 3) + (lane & 7);
        const uint32_t kcol = ((lane >> 3) & 1) * 16;
#pragma unroll
        for (int ks = 0; ks < 4; ks++) {
#pragma unroll
            for (int p = 0; p < 4; p++) {
                uint32_t koff = sw128((p * 16 + krow) * 128 + ks * 32 + kcol);
                uint32_t kh[4], kl[4];
                ldm_x4(kh, stg + 0 * 8192 + koff);
                ldm_x4(kl, stg + 1 * 8192 + koff);
                mma16816(sacc[2 * p],     qh[ks], &kh[0]);
                mma16816(sacc[2 * p],     ql[ks], &kh[0]);
                mma16816(sacc[2 * p],     qh[ks], &kl[0]);
                mma16816(sacc[2 * p + 1], qh[ks], &kh[2]);
                mma16816(sacc[2 * p + 1], ql[ks], &kh[2]);
                mma16816(sacc[2 * p + 1], qh[ks], &kl[2]);
            }
        }

        const int r0 = qw + (lane >> 2), r1 = r0 + 8;
        if (k0g + 63 > qw) {
#pragma unroll
            for (int nf = 0; nf < 8; nf++) {
                int key = k0g + nf * 8 + (lane & 3) * 2;
                if (key     > r0) sacc[nf][0] = -1e30f;
                if (key + 1 > r0) sacc[nf][1] = -1e30f;
                if (key     > r1) sacc[nf][2] = -1e30f;
                if (key + 1 > r1) sacc[nf][3] = -1e30f;
            }
        }

        float mx0 = -1e30f, mx1 = -1e30f;
#pragma unroll
        for (int nf = 0; nf < 8; nf++) {
            mx0 = fmaxf(mx0, fmaxf(sacc[nf][0], sacc[nf][1]));
            mx1 = fmaxf(mx1, fmaxf(sacc[nf][2], sacc[nf][3]));
        }
        mx0 = fmaxf(mx0, __shfl_xor_sync(0xffffffffu, mx0, 1));
        mx0 = fmaxf(mx0, __shfl_xor_sync(0xffffffffu, mx0, 2));
        mx1 = fmaxf(mx1, __shfl_xor_sync(0xffffffffu, mx1, 1));
        mx1 = fmaxf(mx1, __shfl_xor_sync(0xffffffffu, mx1, 2));
        float mn0 = fmaxf(m0, mx0), mn1 = fmaxf(m1, mx1);
        float al0 = fexp(m0 - mn0), al1 = fexp(m1 - mn1);
        m0 = mn0; m1 = mn1;

        float rs0 = 0.0f, rs1 = 0.0f;
#pragma unroll
        for (int nf = 0; nf < 8; nf++) {
            sacc[nf][0] = fexp(sacc[nf][0] - mn0);
            sacc[nf][1] = fexp(sacc[nf][1] - mn0);
            sacc[nf][2] = fexp(sacc[nf][2] - mn1);
            sacc[nf][3] = fexp(sacc[nf][3] - mn1);
            rs0 += sacc[nf][0] + sacc[nf][1];
            rs1 += sacc[nf][2] + sacc[nf][3];
        }
        rs0 += __shfl_xor_sync(0xffffffffu, rs0, 1);
        rs0 += __shfl_xor_sync(0xffffffffu, rs0, 2);
        rs1 += __shfl_xor_sync(0xffffffffu, rs1, 1);
        rs1 += __shfl_xor_sync(0xffffffffu, rs1, 2);
        l0 = l0 * al0 + rs0;
        l1 = l1 * al1 + rs1;

#pragma unroll
        for (int nf = 0; nf < 8; nf++) {
            oacc[nf][0] *= al0; oacc[nf][1] *= al0;
            oacc[nf][2] *= al1; oacc[nf][3] *= al1;
        }

        uint32_t ph[4][4], pl[4][4];
#pragma unroll
        for (int kf = 0; kf < 4; kf++) {
#pragma unroll
            for (int half = 0; half < 2; half++) {
                const float* c = sacc[2 * kf + half];
                uint32_t hA, lA, hB, lB;
                split2(c[0], c[1], hA, lA);
                split2(c[2], c[3], hB, lB);
                ph[kf][half * 2 + 0] = hA;
                ph[kf][half * 2 + 1] = hB;
                pl[kf][half * 2 + 0] = lA;
                pl[kf][half * 2 + 1] = lB;
            }
        }

        const uint32_t vrow = ((lane >> 3) & 1) * 8 + (lane & 7);
        const uint32_t vcol = (lane >> 4) * 16;
#pragma unroll
        for (int kf = 0; kf < 4; kf++) {
#pragma unroll
            for (int nb = 0; nb < 4; nb++) {
                uint32_t voff = sw128((kf * 16 + vrow) * 128 + nb * 32 + vcol);
                uint32_t vh[4], vl[4];
                ldm_x4t(vh, stg + 2 * 8192 + voff);
                ldm_x4t(vl, stg + 3 * 8192 + voff);
                mma16816(oacc[2 * nb],     ph[kf], &vh[0]);
                mma16816(oacc[2 * nb],     pl[kf], &vh[0]);
                mma16816(oacc[2 * nb],     ph[kf], &vl[0]);
                mma16816(oacc[2 * nb + 1], ph[kf], &vh[2]);
                mma16816(oacc[2 * nb + 1], pl[kf], &vh[2]);
                mma16816(oacc[2 * nb + 1], ph[kf], &vl[2]);
            }
        }
    }

    // ---- epilogue: flat bf16 hi/lo splits for the Wo GEMM ----
    const int b = bh >> 4, h = bh & 15;
    const float inv0 = 1.0f / l0, inv1 = 1.0f / l1;
    const int row0 = q0 + w * 16 + (lane >> 2);
    const size_t off0 = ((size_t)(b * SS + row0)) * D_MODEL + h * DK + (lane & 3) * 2;
    const size_t off1 = off0 + 8 * D_MODEL;
#pragma unroll
    for (int nf = 0; nf < 8; nf++) {
        uint32_t H, L;
        split2(oacc[nf][0] * inv0, oacc[nf][1] * inv0, H, L);
        *(uint32_t*)(CxHi + off0 + nf * 8) = H;
        *(uint32_t*)(CxLo + off0 + nf * 8) = L;
        split2(oacc[nf][2] * inv1, oacc[nf][3] * inv1, H, L);
        *(uint32_t*)(CxHi + off1 + nf * 8) = H;
        *(uint32_t*)(CxLo + off1 + nf * 8) = L;
    }
}

// ---------------------------------------------------------------------------
// Launch
// ---------------------------------------------------------------------------
extern "C" void kernel_launch(void* const* d_in, const int* in_sizes, int n_in,
                              void* d_out, int out_size) {
    const float* q  = (const float*)d_in[0];
    const float* k  = (const float*)d_in[1];
    const float* v  = (const float*)d_in[2];
    const float* Wq = (const float*)d_in[4];
    const float* Wk = (const float*)d_in[5];
    const float* Wv = (const float*)d_in[6];
    const float* Wo = (const float*)d_in[7];
    float* out = (float*)d_out;

    __nv_bfloat16 *aqh, *aql, *akh, *akl, *avh, *avl;
    __nv_bfloat16 *wqh, *wql, *wkh, *wkl, *wvh, *wvl, *woh, *wol;
    __nv_bfloat16 *qhh, *qhl, *khh, *khl, *vhh, *vhl, *cxh, *cxl;
    cudaGetSymbolAddress((void**)&aqh, g_aq_hi); cudaGetSymbolAddress((void**)&aql, g_aq_lo);
    cudaGetSymbolAddress((void**)&akh, g_ak_hi); cudaGetSymbolAddress((void**)&akl, g_ak_lo);
    cudaGetSymbolAddress((void**)&avh, g_av_hi); cudaGetSymbolAddress((void**)&avl, g_av_lo);
    cudaGetSymbolAddress((void**)&wqh, g_wq_hi); cudaGetSymbolAddress((void**)&wql, g_wq_lo);
    cudaGetSymbolAddress((void**)&wkh, g_wk_hi); cudaGetSymbolAddress((void**)&wkl, g_wk_lo);
    cudaGetSymbolAddress((void**)&wvh, g_wv_hi); cudaGetSymbolAddress((void**)&wvl, g_wv_lo);
    cudaGetSymbolAddress((void**)&woh, g_wo_hi); cudaGetSymbolAddress((void**)&wol, g_wo_lo);
    cudaGetSymbolAddress((void**)&qhh, g_qh_hi); cudaGetSymbolAddress((void**)&qhl, g_qh_lo);
    cudaGetSymbolAddress((void**)&khh, g_kh_hi); cudaGetSymbolAddress((void**)&khl, g_kh_lo);
    cudaGetSymbolAddress((void**)&vhh, g_vh_hi); cudaGetSymbolAddress((void**)&vhl, g_vh_lo);
    cudaGetSymbolAddress((void**)&cxh, g_cx_hi); cudaGetSymbolAddress((void**)&cxl, g_cx_lo);

    cudaFuncSetAttribute(gemm_tc_kernel<0>, cudaFuncAttributeMaxDynamicSharedMemorySize, GEMM_SMEM);
    cudaFuncSetAttribute(gemm_tc_kernel<1>, cudaFuncAttributeMaxDynamicSharedMemorySize, GEMM_SMEM);
    cudaFuncSetAttribute(gemm_tc_kernel<2>, cudaFuncAttributeMaxDynamicSharedMemorySize, GEMM_SMEM);
    cudaFuncSetAttribute(attn_tc_kernel, cudaFuncAttributeMaxDynamicSharedMemorySize, AT_SMEM);

    const int nA4 = MTOT * D_MODEL / 4;
    const int nW4 = D_MODEL * D_MODEL / 4;
    dim3 ggrid(D_MODEL / 128, MTOT / 128);

    split3_kernel<<<dim3((nA4 + 255) / 256, 3), 256>>>(
        (const float4*)q, (const float4*)k, (const float4*)v,
        (uint2*)aqh, (uint2*)aql, (uint2*)akh, (uint2*)akl, (uint2*)avh, (uint2*)avl, nA4);
    split4_kernel<<<dim3((nW4 + 255) / 256, 4), 256>>>(
        (const float4*)Wq, (const float4*)Wk, (const float4*)Wv, (const float4*)Wo,
        (uint2*)wqh, (uint2*)wql, (uint2*)wkh, (uint2*)wkl,
        (uint2*)wvh, (uint2*)wvl, (uint2*)woh, (uint2*)wol, nW4);

    gemm_tc_kernel<1><<<ggrid, 256, GEMM_SMEM>>>(aqh, aql, wqh, wql, nullptr, qhh, qhl, 0.125f);
    gemm_tc_kernel<1><<<ggrid, 256, GEMM_SMEM>>>(akh, akl, wkh, wkl, nullptr, khh, khl, 1.0f);
    gemm_tc_kernel<2><<<ggrid, 256, GEMM_SMEM>>>(avh, avl, wvh, wvl, nullptr, vhh, vhl, 1.0f);

    attn_tc_kernel<<<dim3(SS / 128, BB * NH), 256, AT_SMEM>>>(qhh, qhl, khh, khl, vhh, vhl, cxh, cxl);

    gemm_tc_kernel<0><<<ggrid, 256, GEMM_SMEM>>>(cxh, cxl, woh, wol, out, nullptr, nullptr, 1.0f);
}

// round 6
// speedup vs baseline: 6.4378x; 1.0399x over previous
#include <cuda_runtime.h>
#include <cuda_bf16.h>
#include <cstdint>
#include <math.h>

#define D_MODEL 1024
#define NH      16
#define DK      64
#define BB      2
#define SS      2048
#define MTOT    (BB * SS)
#define KLOG2   0.41524101186092155f   // log2(10000)/32

// ---------------------------------------------------------------------------
// Scratch (allocation-free rule: __device__ globals)
// ---------------------------------------------------------------------------
__device__ __nv_bfloat16 g_aq_hi[MTOT * D_MODEL], g_aq_lo[MTOT * D_MODEL];
__device__ __nv_bfloat16 g_ak_hi[MTOT * D_MODEL], g_ak_lo[MTOT * D_MODEL];
__device__ __nv_bfloat16 g_av_hi[MTOT * D_MODEL], g_av_lo[MTOT * D_MODEL];
__device__ __nv_bfloat16 g_wq_hi[D_MODEL * D_MODEL], g_wq_lo[D_MODEL * D_MODEL];
__device__ __nv_bfloat16 g_wk_hi[D_MODEL * D_MODEL], g_wk_lo[D_MODEL * D_MODEL];
__device__ __nv_bfloat16 g_wv_hi[D_MODEL * D_MODEL], g_wv_lo[D_MODEL * D_MODEL];
__device__ __nv_bfloat16 g_wo_hi[D_MODEL * D_MODEL], g_wo_lo[D_MODEL * D_MODEL];
__device__ __nv_bfloat16 g_qh_hi[MTOT * D_MODEL], g_qh_lo[MTOT * D_MODEL];
__device__ __nv_bfloat16 g_kh_hi[MTOT * D_MODEL], g_kh_lo[MTOT * D_MODEL];
__device__ __nv_bfloat16 g_vh_hi[MTOT * D_MODEL], g_vh_lo[MTOT * D_MODEL];
__device__ __nv_bfloat16 g_cx_hi[MTOT * D_MODEL], g_cx_lo[MTOT * D_MODEL];

// ---------------------------------------------------------------------------
// Portable PTX helpers
// ---------------------------------------------------------------------------
__device__ __forceinline__ uint32_t smem_u32(const void* p) {
    uint32_t a;
    asm("{ .reg .u64 t; cvta.to.shared.u64 t, %1; cvt.u32.u64 %0, t; }" : "=r"(a) : "l"(p));
    return a;
}
#define CP_ASYNC16(dst, src) \
    asm volatile("cp.async.cg.shared.global [%0], [%1], 16;" :: "r"(dst), "l"(src))
#define CP_COMMIT() asm volatile("cp.async.commit_group;" ::: "memory")
#define CP_WAIT(n)  asm volatile("cp.async.wait_group %0;" :: "n"(n) : "memory")

__device__ __forceinline__ void ldm_x4(uint32_t* r, uint32_t addr) {
    asm volatile("ldmatrix.sync.aligned.m8n8.x4.shared.b16 {%0,%1,%2,%3}, [%4];"
                 : "=r"(r[0]), "=r"(r[1]), "=r"(r[2]), "=r"(r[3]) : "r"(addr));
}
__device__ __forceinline__ void ldm_x4t(uint32_t* r, uint32_t addr) {
    asm volatile("ldmatrix.sync.aligned.m8n8.x4.trans.shared.b16 {%0,%1,%2,%3}, [%4];"
                 : "=r"(r[0]), "=r"(r[1]), "=r"(r[2]), "=r"(r[3]) : "r"(addr));
}
__device__ __forceinline__ void mma16816(float* d, const uint32_t* a, const uint32_t* b) {
    asm volatile(
        "mma.sync.aligned.m16n8k16.row.col.f32.bf16.bf16.f32 "
        "{%0,%1,%2,%3}, {%4,%5,%6,%7}, {%8,%9}, {%0,%1,%2,%3};"
        : "+f"(d[0]), "+f"(d[1]), "+f"(d[2]), "+f"(d[3])
        : "r"(a[0]), "r"(a[1]), "r"(a[2]), "r"(a[3]), "r"(b[0]), "r"(b[1]));
}
__device__ __forceinline__ uint32_t sw64(uint32_t off)  { return off ^ ((off >> 3) & 0x30); }
__device__ __forceinline__ uint32_t sw128(uint32_t off) { return off ^ ((off >> 3) & 0x70); }

__device__ __forceinline__ uint32_t pack_bf16(float lo, float hi) {
    uint32_t r;
    asm("cvt.rn.bf16x2.f32 %0, %1, %2;" : "=r"(r) : "f"(hi), "f"(lo));
    return r;
}
__device__ __forceinline__ void split2(float a, float b, uint32_t& H, uint32_t& L) {
    uint32_t h = pack_bf16(a, b);
    float ha = __int_as_float((int)(h << 16));
    float hb = __int_as_float((int)(h & 0xFFFF0000u));
    H = h;
    L = pack_bf16(a - ha, b - hb);
}
__device__ __forceinline__ float fexp(float x) {
    float t = fmaxf(x * 1.4426950408889634f, -120.0f);
    float y = t + 12582912.0f;
    int   i = __float_as_int(y) - 0x4B400000;
    float f = t - (y - 12582912.0f);
    float p =         1.3333558146e-3f;
    p = fmaf(p, f, 9.6181291076e-3f);
    p = fmaf(p, f, 5.5504108664e-2f);
    p = fmaf(p, f, 2.4022650696e-1f);
    p = fmaf(p, f, 6.9314718056e-1f);
    p = fmaf(p, f, 1.0f);
    return __int_as_float(__float_as_int(p) + (i << 23));
}

// ---------------------------------------------------------------------------
// Fused input splits
// ---------------------------------------------------------------------------
__device__ __forceinline__ void do_split4(float4 v, uint2& H, uint2& L) {
    __nv_bfloat16 h0 = __float2bfloat16(v.x), h1 = __float2bfloat16(v.y);
    __nv_bfloat16 h2 = __float2bfloat16(v.z), h3 = __float2bfloat16(v.w);
    __nv_bfloat16 l0 = __float2bfloat16(v.x - __bfloat162float(h0));
    __nv_bfloat16 l1 = __float2bfloat16(v.y - __bfloat162float(h1));
    __nv_bfloat16 l2 = __float2bfloat16(v.z - __bfloat162float(h2));
    __nv_bfloat16 l3 = __float2bfloat16(v.w - __bfloat162float(h3));
    H.x = (uint32_t)__bfloat16_as_ushort(h0) | ((uint32_t)__bfloat16_as_ushort(h1) << 16);
    H.y = (uint32_t)__bfloat16_as_ushort(h2) | ((uint32_t)__bfloat16_as_ushort(h3) << 16);
    L.x = (uint32_t)__bfloat16_as_ushort(l0) | ((uint32_t)__bfloat16_as_ushort(l1) << 16);
    L.y = (uint32_t)__bfloat16_as_ushort(l2) | ((uint32_t)__bfloat16_as_ushort(l3) << 16);
}

__global__ void split3_kernel(const float4* __restrict__ A, const float4* __restrict__ B,
                              const float4* __restrict__ C, int n4) {
    int i = blockIdx.x * blockDim.x + threadIdx.x;
    if (i >= n4) return;
    const float4* src = (blockIdx.y == 0) ? A : (blockIdx.y == 1) ? B : C;
    uint2* dh = (blockIdx.y == 0) ? (uint2*)g_aq_hi : (blockIdx.y == 1) ? (uint2*)g_ak_hi : (uint2*)g_av_hi;
    uint2* dl = (blockIdx.y == 0) ? (uint2*)g_aq_lo : (blockIdx.y == 1) ? (uint2*)g_ak_lo : (uint2*)g_av_lo;
    uint2 H, L;
    do_split4(src[i], H, L);
    dh[i] = H;
    dl[i] = L;
}

__global__ void split4_kernel(const float4* __restrict__ A, const float4* __restrict__ B,
                              const float4* __restrict__ C, const float4* __restrict__ D, int n4) {
    int i = blockIdx.x * blockDim.x + threadIdx.x;
    if (i >= n4) return;
    int s = blockIdx.y;
    const float4* src = (s == 0) ? A : (s == 1) ? B : (s == 2) ? C : D;
    uint2* oh = (s == 0) ? (uint2*)g_wq_hi : (s == 1) ? (uint2*)g_wk_hi : (s == 2) ? (uint2*)g_wv_hi : (uint2*)g_wo_hi;
    uint2* ol = (s == 0) ? (uint2*)g_wq_lo : (s == 1) ? (uint2*)g_wk_lo : (s == 2) ? (uint2*)g_wv_lo : (uint2*)g_wo_lo;
    uint2 H, L;
    do_split4(src[i], H, L);
    oh[i] = H;
    ol[i] = L;
}

// ---------------------------------------------------------------------------
// GEMM core: shared mainloop body (A @ W^T, bf16 3-term split)
// ---------------------------------------------------------------------------
#define GK        1024
#define BKC       32
#define NCH       (GK / BKC)
#define TILE8K    8192
#define STAGE_B   (4 * TILE8K)
#define NSTG      3
#define GEMM_SMEM (NSTG * STAGE_B)

struct GemmCtx {
    uint32_t smb;
    uint32_t aoff[2][2], boff[4][2];
    const __nv_bfloat16* gb[4];
    int lrow, lc;
};

__device__ __forceinline__ void gemm_mainloop(GemmCtx& cx, float acc[2][8][4]) {
    auto load_stage = [&](int st, int ch) {
        const uint32_t sb = cx.smb + st * STAGE_B;
#pragma unroll
        for (int j = 0; j < 8; j++) {
            const int tile = j >> 1;
            const int rh = (j & 1) * 64 + cx.lrow;
            const __nv_bfloat16* g = cx.gb[tile] + (size_t)rh * GK + ch * BKC + cx.lc * 8;
            const uint32_t dst = sb + tile * TILE8K + sw64(rh * 64 + cx.lc * 16);
            CP_ASYNC16(dst, g);
        }
        CP_COMMIT();
    };

    load_stage(0, 0);
    load_stage(1, 1);

    for (int ch = 0; ch < NCH; ch++) {
        if (ch < NCH - 2) { CP_WAIT(1); } else { CP_WAIT(0); }
        __syncthreads();
        if (ch + 2 < NCH) load_stage((ch + 2) % NSTG, ch + 2);

        const uint32_t sb = cx.smb + (ch % NSTG) * STAGE_B;
#pragma unroll
        for (int ks = 0; ks < 2; ks++) {
            uint32_t ah[2][4], al[2][4];
#pragma unroll
            for (int mf = 0; mf < 2; mf++) {
                ldm_x4(ah[mf], sb + cx.aoff[mf][ks]);
                ldm_x4(al[mf], sb + TILE8K + cx.aoff[mf][ks]);
            }
#pragma unroll
            for (int nh = 0; nh < 2; nh++) {
                uint32_t bh[2][4], bl[2][4];
#pragma unroll
                for (int p = 0; p < 2; p++) {
                    ldm_x4(bh[p], sb + 2 * TILE8K + cx.boff[nh * 2 + p][ks]);
                    ldm_x4(bl[p], sb + 3 * TILE8K + cx.boff[nh * 2 + p][ks]);
                }
#pragma unroll
                for (int mf = 0; mf < 2; mf++)
#pragma unroll
                    for (int p = 0; p < 2; p++)
#pragma unroll
                        for (int q = 0; q < 2; q++) {
                            const int nf = nh * 4 + p * 2 + q;
                            mma16816(acc[mf][nf], ah[mf], &bh[p][q * 2]);
                            mma16816(acc[mf][nf], al[mf], &bh[p][q * 2]);
                            mma16816(acc[mf][nf], ah[mf], &bl[p][q * 2]);
                        }
            }
        }
    }
}

__device__ __forceinline__ void gemm_setup(GemmCtx& cx, const char* smc, int t,
                                           const __nv_bfloat16* Ahi, const __nv_bfloat16* Alo,
                                           const __nv_bfloat16* Bhi, const __nv_bfloat16* Blo,
                                           int m0, int n0) {
    cx.smb = smem_u32(smc);
    const int lane = t & 31, wid = t >> 5;
    const int warpM = wid >> 1, warpN = wid & 1;
    cx.lrow = t >> 2;
    cx.lc = t & 3;
    cx.gb[0] = Ahi + (size_t)m0 * GK;
    cx.gb[1] = Alo + (size_t)m0 * GK;
    cx.gb[2] = Bhi + (size_t)n0 * GK;
    cx.gb[3] = Blo + (size_t)n0 * GK;
#pragma unroll
    for (int mf = 0; mf < 2; mf++)
#pragma unroll
        for (int ks = 0; ks < 2; ks++)
            cx.aoff[mf][ks] = sw64((warpM * 32 + mf * 16 + (lane & 15)) * 64
                                   + ks * 32 + (lane >> 4) * 16);
#pragma unroll
    for (int p = 0; p < 4; p++)
#pragma unroll
        for (int ks = 0; ks < 2; ks++)
            cx.boff[p][ks] = sw64((warpN * 64 + p * 16 + ((lane >> 4) << 3) + (lane & 7)) * 64
                                  + ks * 32 + ((lane >> 3) & 1) * 16);
}

// ---------------------------------------------------------------------------
// Merged QKV projection GEMM: blockIdx.z selects {Q, K, V}.
// Epilogue: z<2 -> RoPE + per-head split; z==2 -> per-head split.
// ---------------------------------------------------------------------------
__global__ void __launch_bounds__(256, 2) gemm_qkv_kernel() {
    extern __shared__ char smc[];
    const int t = threadIdx.x;
    const int lane = t & 31, wid = t >> 5;
    const int warpM = wid >> 1, warpN = wid & 1;
    const int m0 = blockIdx.y * 128;
    const int n0 = blockIdx.x * 128;
    const int z = blockIdx.z;

    const __nv_bfloat16 *Ahi, *Alo, *Bhi, *Blo;
    __nv_bfloat16 *Ohi, *Olo;
    float scale;
    if (z == 0) {
        Ahi = g_aq_hi; Alo = g_aq_lo; Bhi = g_wq_hi; Blo = g_wq_lo;
        Ohi = g_qh_hi; Olo = g_qh_lo; scale = 0.125f;
    } else if (z == 1) {
        Ahi = g_ak_hi; Alo = g_ak_lo; Bhi = g_wk_hi; Blo = g_wk_lo;
        Ohi = g_kh_hi; Olo = g_kh_lo; scale = 1.0f;
    } else {
        Ahi = g_av_hi; Alo = g_av_lo; Bhi = g_wv_hi; Blo = g_wv_lo;
        Ohi = g_vh_hi; Olo = g_vh_lo; scale = 1.0f;
    }

    GemmCtx cx;
    gemm_setup(cx, smc, t, Ahi, Alo, Bhi, Blo, m0, n0);

    float acc[2][8][4];
#pragma unroll
    for (int mf = 0; mf < 2; mf++)
#pragma unroll
        for (int nf = 0; nf < 8; nf++)
#pragma unroll
            for (int r = 0; r < 4; r++) acc[mf][nf][r] = 0.0f;

    gemm_mainloop(cx, acc);

    const int rbase = m0 + warpM * 32 + (lane >> 2);
    const int h = (n0 >> 6) + warpN;
    if (z < 2) {
        // RoPE + per-head split: pair (d, d+32) = (nf, nf+4)
#pragma unroll
        for (int mf = 0; mf < 2; mf++)
#pragma unroll
            for (int r2 = 0; r2 < 2; r2++) {
                const int gr = rbase + mf * 16 + r2 * 8;
                const int s = gr & (SS - 1), b = gr >> 11;
                const float fs = (float)s;
                __nv_bfloat16* oh = Ohi + ((size_t)(b * NH + h) * SS + s) * DK;
                __nv_bfloat16* ol = Olo + ((size_t)(b * NH + h) * SS + s) * DK;
#pragma unroll
                for (int nf = 0; nf < 4; nf++) {
                    const int i0 = (lane & 3) * 2 + nf * 8;
                    float x1a = acc[mf][nf][2 * r2],     x1b = acc[mf][nf][2 * r2 + 1];
                    float x2a = acc[mf][nf + 4][2 * r2], x2b = acc[mf][nf + 4][2 * r2 + 1];
                    float sa, ca, sb2, cb;
                    sincosf(fs * exp2f(-(float)i0 * KLOG2), &sa, &ca);
                    sincosf(fs * exp2f(-(float)(i0 + 1) * KLOG2), &sb2, &cb);
                    float y1a = (x1a * ca - x2a * sa) * scale;
                    float y1b = (x1b * cb - x2b * sb2) * scale;
                    float y2a = (x2a * ca + x1a * sa) * scale;
                    float y2b = (x2b * cb + x1b * sb2) * scale;
                    uint32_t H, L;
                    split2(y1a, y1b, H, L);
                    *(uint32_t*)(oh + i0) = H;
                    *(uint32_t*)(ol + i0) = L;
                    split2(y2a, y2b, H, L);
                    *(uint32_t*)(oh + i0 + 32) = H;
                    *(uint32_t*)(ol + i0 + 32) = L;
                }
            }
    } else {
#pragma unroll
        for (int mf = 0; mf < 2; mf++)
#pragma unroll
            for (int r2 = 0; r2 < 2; r2++) {
                const int gr = rbase + mf * 16 + r2 * 8;
                const int s = gr & (SS - 1), b = gr >> 11;
                __nv_bfloat16* oh = Ohi + ((size_t)(b * NH + h) * SS + s) * DK;
                __nv_bfloat16* ol = Olo + ((size_t)(b * NH + h) * SS + s) * DK;
#pragma unroll
                for (int nf = 0; nf < 8; nf++) {
                    const int d = (lane & 3) * 2 + nf * 8;
                    uint32_t H, L;
                    split2(acc[mf][nf][2 * r2], acc[mf][nf][2 * r2 + 1], H, L);
                    *(uint32_t*)(oh + d) = H;
                    *(uint32_t*)(ol + d) = L;
                }
            }
    }
}

// ---------------------------------------------------------------------------
// Output GEMM: ctx_split @ Wo^T -> fp32 out
// ---------------------------------------------------------------------------
__global__ void __launch_bounds__(256, 2) gemm_out_kernel(float* __restrict__ C) {
    extern __shared__ char smc[];
    const int t = threadIdx.x;
    const int lane = t & 31, wid = t >> 5;
    const int warpM = wid >> 1, warpN = wid & 1;
    const int m0 = blockIdx.y * 128;
    const int n0 = blockIdx.x * 128;

    GemmCtx cx;
    gemm_setup(cx, smc, t, g_cx_hi, g_cx_lo, g_wo_hi, g_wo_lo, m0, n0);

    float acc[2][8][4];
#pragma unroll
    for (int mf = 0; mf < 2; mf++)
#pragma unroll
        for (int nf = 0; nf < 8; nf++)
#pragma unroll
            for (int r = 0; r < 4; r++) acc[mf][nf][r] = 0.0f;

    gemm_mainloop(cx, acc);

    const int rbase = m0 + warpM * 32 + (lane >> 2);
    const int cbase = n0 + warpN * 64 + (lane & 3) * 2;
#pragma unroll
    for (int mf = 0; mf < 2; mf++)
#pragma unroll
        for (int nf = 0; nf < 8; nf++) {
            const int row = rbase + mf * 16;
            const int col = cbase + nf * 8;
            float2 v0 = {acc[mf][nf][0], acc[mf][nf][1]};
            float2 v1 = {acc[mf][nf][2], acc[mf][nf][3]};
            *(float2*)(C + (size_t)row * D_MODEL + col) = v0;
            *(float2*)(C + (size_t)(row + 8) * D_MODEL + col) = v1;
        }
}

// ---------------------------------------------------------------------------
// Tensor-core causal flash attention (R5-proven); writes flat bf16 splits.
// ---------------------------------------------------------------------------
#define AT_QHI   0
#define AT_QLO   16384
#define AT_STG   32768
#define AT_SMEM  (32768 + 2 * 32768)

__global__ void __launch_bounds__(256, 1) attn_tc_kernel() {
    extern __shared__ char smc[];
    const uint32_t smb = smem_u32(smc);
    const int t = threadIdx.x, lane = t & 31, w = t >> 5;
    const int bx = (int)gridDim.x - 1 - (int)blockIdx.x;
    const int bh = blockIdx.y;
    const int q0 = bx * 128;
    const int ntk = 2 * bx + 2;
    const size_t hoff = (size_t)bh * SS * DK;

    const __nv_bfloat16* Qhi = g_qh_hi;
    const __nv_bfloat16* Qlo = g_qh_lo;
    const __nv_bfloat16* Khi = g_kh_hi;
    const __nv_bfloat16* Klo = g_kh_lo;
    const __nv_bfloat16* Vhi = g_vh_hi;
    const __nv_bfloat16* Vlo = g_vh_lo;

    {
        int row = t >> 1;
        const __nv_bfloat16* qh = Qhi + hoff + (size_t)(q0 + row) * DK;
        const __nv_bfloat16* ql = Qlo + hoff + (size_t)(q0 + row) * DK;
#pragma unroll
        for (int j = 0; j < 4; j++) {
            int slot = (t & 1) * 4 + j;
            uint32_t sw = sw128(row * 128 + slot * 16);
            CP_ASYNC16(smb + AT_QHI + sw, qh + slot * 8);
            CP_ASYNC16(smb + AT_QLO + sw, ql + slot * 8);
        }
    }
    const int kvrow = t >> 2;
    const int kvs0 = t & 3;
    auto load_kv = [&](int st, int kt) {
        const uint32_t sb = smb + AT_STG + st * 32768;
        const size_t g = hoff + (size_t)(kt * 64 + kvrow) * DK;
#pragma unroll
        for (int j = 0; j < 2; j++) {
            int slot = kvs0 + j * 4;
            uint32_t sw = sw128(kvrow * 128 + slot * 16);
            CP_ASYNC16(sb + 0 * 8192 + sw, Khi + g + slot * 8);
            CP_ASYNC16(sb + 1 * 8192 + sw, Klo + g + slot * 8);
            CP_ASYNC16(sb + 2 * 8192 + sw, Vhi + g + slot * 8);
            CP_ASYNC16(sb + 3 * 8192 + sw, Vlo + g + slot * 8);
        }
        CP_COMMIT();
    };

    load_kv(0, 0);
    CP_WAIT(0);
    __syncthreads();

    uint32_t qh[4][4], ql[4][4];
    {
        uint32_t base = (w * 16 + (lane & 15)) * 128 + (lane >> 4) * 16;
#pragma unroll
        for (int ks = 0; ks < 4; ks++) {
            uint32_t sw = sw128(base + ks * 32);
            ldm_x4(qh[ks], smb + AT_QHI + sw);
            ldm_x4(ql[ks], smb + AT_QLO + sw);
        }
    }

    float oacc[8][4];
#pragma unroll
    for (int nf = 0; nf < 8; nf++)
#pragma unroll
        for (int r = 0; r < 4; r++) oacc[nf][r] = 0.0f;
    float m0 = -1e30f, m1 = -1e30f, l0 = 0.0f, l1 = 0.0f;

    const int qw = q0 + w * 16;

    for (int ch = 0; ch < ntk; ch++) {
        __syncthreads();
        if (ch + 1 < ntk) load_kv((ch + 1) & 1, ch + 1);
        if (ch + 1 < ntk) { CP_WAIT(1); } else { CP_WAIT(0); }
        __syncthreads();

        const int k0g = ch * 64;
        if (k0g > qw + 15) continue;

        const uint32_t stg = smb + AT_STG + (ch & 1) * 32768;

        float sacc[8][4];
#pragma unroll
        for (int nf = 0; nf < 8; nf++)
#pragma unroll
            for (int r = 0; r < 4; r++) sacc[nf][r] = 0.0f;

        const uint32_t krow = ((lane >> 4) << 3) + (lane & 7);
        const uint32_t kcol = ((lane >> 3) & 1) * 16;
#pragma unroll
        for (int ks = 0; ks < 4; ks++) {
#pragma unroll
            for (int p = 0; p < 4; p++) {
                uint32_t koff = sw128((p * 16 + krow) * 128 + ks * 32 + kcol);
                uint32_t kh[4], kl[4];
                ldm_x4(kh, stg + 0 * 8192 + koff);
                ldm_x4(kl, stg + 1 * 8192 + koff);
                mma16816(sacc[2 * p],     qh[ks], &kh[0]);
                mma16816(sacc[2 * p],     ql[ks], &kh[0]);
                mma16816(sacc[2 * p],     qh[ks], &kl[0]);
                mma16816(sacc[2 * p + 1], qh[ks], &kh[2]);
                mma16816(sacc[2 * p + 1], ql[ks], &kh[2]);
                mma16816(sacc[2 * p + 1], qh[ks], &kl[2]);
            }
        }

        const int r0 = qw + (lane >> 2), r1 = r0 + 8;
        if (k0g + 63 > qw) {
#pragma unroll
            for (int nf = 0; nf < 8; nf++) {
                int key = k0g + nf * 8 + (lane & 3) * 2;
                if (key     > r0) sacc[nf][0] = -1e30f;
                if (key + 1 > r0) sacc[nf][1] = -1e30f;
                if (key     > r1) sacc[nf][2] = -1e30f;
                if (key + 1 > r1) sacc[nf][3] = -1e30f;
            }
        }

        float mx0 = -1e30f, mx1 = -1e30f;
#pragma unroll
        for (int nf = 0; nf < 8; nf++) {
            mx0 = fmaxf(mx0, fmaxf(sacc[nf][0], sacc[nf][1]));
            mx1 = fmaxf(mx1, fmaxf(sacc[nf][2], sacc[nf][3]));
        }
        mx0 = fmaxf(mx0, __shfl_xor_sync(0xffffffffu, mx0, 1));
        mx0 = fmaxf(mx0, __shfl_xor_sync(0xffffffffu, mx0, 2));
        mx1 = fmaxf(mx1, __shfl_xor_sync(0xffffffffu, mx1, 1));
        mx1 = fmaxf(mx1, __shfl_xor_sync(0xffffffffu, mx1, 2));
        float mn0 = fmaxf(m0, mx0), mn1 = fmaxf(m1, mx1);
        float al0 = fexp(m0 - mn0), al1 = fexp(m1 - mn1);
        m0 = mn0; m1 = mn1;

        float rs0 = 0.0f, rs1 = 0.0f;
#pragma unroll
        for (int nf = 0; nf < 8; nf++) {
            sacc[nf][0] = fexp(sacc[nf][0] - mn0);
            sacc[nf][1] = fexp(sacc[nf][1] - mn0);
            sacc[nf][2] = fexp(sacc[nf][2] - mn1);
            sacc[nf][3] = fexp(sacc[nf][3] - mn1);
            rs0 += sacc[nf][0] + sacc[nf][1];
            rs1 += sacc[nf][2] + sacc[nf][3];
        }
        rs0 += __shfl_xor_sync(0xffffffffu, rs0, 1);
        rs0 += __shfl_xor_sync(0xffffffffu, rs0, 2);
        rs1 += __shfl_xor_sync(0xffffffffu, rs1, 1);
        rs1 += __shfl_xor_sync(0xffffffffu, rs1, 2);
        l0 = l0 * al0 + rs0;
        l1 = l1 * al1 + rs1;

#pragma unroll
        for (int nf = 0; nf < 8; nf++) {
            oacc[nf][0] *= al0; oacc[nf][1] *= al0;
            oacc[nf][2] *= al1; oacc[nf][3] *= al1;
        }

        uint32_t ph[4][4], pl[4][4];
#pragma unroll
        for (int kf = 0; kf < 4; kf++) {
#pragma unroll
            for (int half = 0; half < 2; half++) {
                const float* c = sacc[2 * kf + half];
                uint32_t hA, lA, hB, lB;
                split2(c[0], c[1], hA, lA);
                split2(c[2], c[3], hB, lB);
                ph[kf][half * 2 + 0] = hA;
                ph[kf][half * 2 + 1] = hB;
                pl[kf][half * 2 + 0] = lA;
                pl[kf][half * 2 + 1] = lB;
            }
        }

        const uint32_t vrow = ((lane >> 3) & 1) * 8 + (lane & 7);
        const uint32_t vcol = (lane >> 4) * 16;
#pragma unroll
        for (int kf = 0; kf < 4; kf++) {
#pragma unroll
            for (int nb = 0; nb < 4; nb++) {
                uint32_t voff = sw128((kf * 16 + vrow) * 128 + nb * 32 + vcol);
                uint32_t vh[4], vl[4];
                ldm_x4t(vh, stg + 2 * 8192 + voff);
                ldm_x4t(vl, stg + 3 * 8192 + voff);
                mma16816(oacc[2 * nb],     ph[kf], &vh[0]);
                mma16816(oacc[2 * nb],     pl[kf], &vh[0]);
                mma16816(oacc[2 * nb],     ph[kf], &vl[0]);
                mma16816(oacc[2 * nb + 1], ph[kf], &vh[2]);
                mma16816(oacc[2 * nb + 1], pl[kf], &vh[2]);
                mma16816(oacc[2 * nb + 1], ph[kf], &vl[2]);
            }
        }
    }

    const int b = bh >> 4, h = bh & 15;
    const float inv0 = 1.0f / l0, inv1 = 1.0f / l1;
    const int row0 = q0 + w * 16 + (lane >> 2);
    const size_t off0 = ((size_t)(b * SS + row0)) * D_MODEL + h * DK + (lane & 3) * 2;
    const size_t off1 = off0 + 8 * D_MODEL;
#pragma unroll
    for (int nf = 0; nf < 8; nf++) {
        uint32_t H, L;
        split2(oacc[nf][0] * inv0, oacc[nf][1] * inv0, H, L);
        *(uint32_t*)(g_cx_hi + off0 + nf * 8) = H;
        *(uint32_t*)(g_cx_lo + off0 + nf * 8) = L;
        split2(oacc[nf][2] * inv1, oacc[nf][3] * inv1, H, L);
        *(uint32_t*)(g_cx_hi + off1 + nf * 8) = H;
        *(uint32_t*)(g_cx_lo + off1 + nf * 8) = L;
    }
}

// ---------------------------------------------------------------------------
// Launch
// ---------------------------------------------------------------------------
extern "C" void kernel_launch(void* const* d_in, const int* in_sizes, int n_in,
                              void* d_out, int out_size) {
    const float* q  = (const float*)d_in[0];
    const float* k  = (const float*)d_in[1];
    const float* v  = (const float*)d_in[2];
    const float* Wq = (const float*)d_in[4];
    const float* Wk = (const float*)d_in[5];
    const float* Wv = (const float*)d_in[6];
    const float* Wo = (const float*)d_in[7];
    float* out = (float*)d_out;

    cudaFuncSetAttribute(gemm_qkv_kernel, cudaFuncAttributeMaxDynamicSharedMemorySize, GEMM_SMEM);
    cudaFuncSetAttribute(gemm_out_kernel, cudaFuncAttributeMaxDynamicSharedMemorySize, GEMM_SMEM);
    cudaFuncSetAttribute(attn_tc_kernel, cudaFuncAttributeMaxDynamicSharedMemorySize, AT_SMEM);

    const int nA4 = MTOT * D_MODEL / 4;
    const int nW4 = D_MODEL * D_MODEL / 4;

    split3_kernel<<<dim3((nA4 + 255) / 256, 3), 256>>>(
        (const float4*)q, (const float4*)k, (const float4*)v, nA4);
    split4_kernel<<<dim3((nW4 + 255) / 256, 4), 256>>>(
        (const float4*)Wq, (const float4*)Wk, (const float4*)Wv, (const float4*)Wo, nW4);

    gemm_qkv_kernel<<<dim3(D_MODEL / 128, MTOT / 128, 3), 256, GEMM_SMEM>>>();

    attn_tc_kernel<<<dim3(SS / 128, BB * NH), 256, AT_SMEM>>>();

    gemm_out_kernel<<<dim3(D_MODEL / 128, MTOT / 128), 256, GEMM_SMEM>>>(out);
}